// round 5
// baseline (speedup 1.0000x reference)
#include <cuda_runtime.h>

#define B 8
#define L 512
#define HID 768
#define NH 12
#define D 64
#define TH 32
#define TE 64
#define TT 96          // TH + TE
#define BH (B*NH)      // 96
#define ROWS (B*L)     // 4096

typedef unsigned long long ull;

__device__ __forceinline__ ull pack2(float lo, float hi) {
    ull r; asm("mov.b64 %0, {%1,%2};" : "=l"(r) : "f"(lo), "f"(hi)); return r;
}
__device__ __forceinline__ ull ffma2(ull a, ull b, ull c) {
    ull d; asm("fma.rn.f32x2 %0, %1, %2, %3;" : "=l"(d) : "l"(a), "l"(b), "l"(c)); return d;
}
__device__ __forceinline__ float2 unpack2(ull v) {
    float2 f; asm("mov.b64 {%0,%1}, %2;" : "=f"(f.x), "=f"(f.y) : "l"(v)); return f;
}

// ---------------- scratch (__device__ globals; no allocs allowed) ----------
__device__ float g_Q[BH*L*D];     // [bh][l][d]
__device__ float g_K[BH*L*D];
__device__ float g_V[BH*L*D];
__device__ float g_P[BH*L*TT];    // per-row bias table
__device__ float g_AO[ROWS*HID];  // attention output pre-Wo, [b*l][h*64+d]

// ---------------- GEMM: C = A[4096,768] @ W[768,768] + bias ----------------
// 128x128 tile, 256 threads, 8x8 per-thread register tile, f32x2 FMAs.
#define GM 128
#define GN 128
#define GK 16

__global__ __launch_bounds__(256, 2) void gemm_kernel(
    const float* __restrict__ A, const float* __restrict__ W,
    const float* __restrict__ bias, float* __restrict__ Cout, int headLayout)
{
    __shared__ float As[GK][GM + 4];   // A tile transposed: As[k][row]
    __shared__ float Bs[GK][GN];       // Bs[k][col]
    const int tid = threadIdx.x;
    const int tx = tid & 15;           // col group: 8 cols each
    const int ty = tid >> 4;           // row group: 8 rows each
    const int row0 = blockIdx.x * GM, col0 = blockIdx.y * GN;

    ull acc[8][4];
#pragma unroll
    for (int r = 0; r < 8; ++r)
#pragma unroll
        for (int c = 0; c < 4; ++c) acc[r][c] = 0ull;

    for (int k0 = 0; k0 < HID; k0 += GK) {
#pragma unroll
        for (int lidx = 0; lidx < (GM * GK) / 256; ++lidx) {
            int idx = tid + lidx * 256;
            int r = idx >> 4, kk = idx & 15;
            As[kk][r] = A[(size_t)(row0 + r) * HID + k0 + kk];
        }
#pragma unroll
        for (int lidx = 0; lidx < (GK * GN) / 256; ++lidx) {
            int idx = tid + lidx * 256;
            int kk = idx >> 7, c = idx & 127;
            Bs[kk][c] = W[(size_t)(k0 + kk) * HID + col0 + c];
        }
        __syncthreads();
#pragma unroll
        for (int kk = 0; kk < GK; ++kk) {
            float4 a0 = *(const float4*)&As[kk][ty * 8];
            float4 a1 = *(const float4*)&As[kk][ty * 8 + 4];
            float4 b0 = *(const float4*)&Bs[kk][tx * 8];
            float4 b1 = *(const float4*)&Bs[kk][tx * 8 + 4];
            // b pairs alias register pairs directly (no pack instruction)
            ull bb[4];
            bb[0] = ((const ull*)&b0)[0]; bb[1] = ((const ull*)&b0)[1];
            bb[2] = ((const ull*)&b1)[0]; bb[3] = ((const ull*)&b1)[1];
            float a[8] = {a0.x, a0.y, a0.z, a0.w, a1.x, a1.y, a1.z, a1.w};
#pragma unroll
            for (int r = 0; r < 8; ++r) {
                ull aa = pack2(a[r], a[r]);
#pragma unroll
                for (int c = 0; c < 4; ++c) acc[r][c] = ffma2(aa, bb[c], acc[r][c]);
            }
        }
        __syncthreads();
    }

#pragma unroll
    for (int r = 0; r < 8; ++r) {
        int row = row0 + ty * 8 + r;
#pragma unroll
        for (int c = 0; c < 4; ++c) {
            float2 v2 = unpack2(acc[r][c]);
            int col = col0 + tx * 8 + c * 2;
#pragma unroll
            for (int u = 0; u < 2; ++u) {
                float v = (u ? v2.y : v2.x) + bias[col + u];
                int cc = col + u;
                if (headLayout) {
                    int bb2 = row >> 9, ll = row & 511, h = cc >> 6, dd = cc & 63;
                    Cout[(((size_t)bb2 * NH + h) * L + ll) * D + dd] = v;
                } else {
                    Cout[(size_t)row * HID + cc] = v;
                }
            }
        }
    }
}

// ------------- bias-table projection: P[bh][l][t] ---------------------------
// P[l][t] = q_l . EQ[t] + k_l . EK[t]
// 2x2 register tiling with float4 LDS (attacks the measured 72% L1 bound).
#define EPAD 68

__global__ __launch_bounds__(256) void proj_kernel(
    const float* __restrict__ qh, const float* __restrict__ qe,
    const float* __restrict__ kh, const float* __restrict__ ke)
{
    extern __shared__ float sm[];
    float* qs = sm;                  // 64*64
    float* ks = qs + 64 * 64;        // 64*64
    float* EQ = ks + 64 * 64;        // 96*EPAD
    float* EK = EQ + TT * EPAD;      // 96*EPAD

    const int bh = blockIdx.x;
    const int h  = bh % NH;
    const int l0 = blockIdx.y * 64;
    const int tid = threadIdx.x;

    const float* Qp = g_Q + ((size_t)bh * L + l0) * D;
    const float* Kp = g_K + ((size_t)bh * L + l0) * D;
    for (int idx = tid; idx < 64 * D; idx += 256) { qs[idx] = Qp[idx]; ks[idx] = Kp[idx]; }
    for (int idx = tid; idx < TT * D; idx += 256) {
        int t = idx >> 6, dd = idx & 63;
        float eq, ek;
        if (t < TH) { eq = qh[(size_t)t * HID + h * D + dd]; ek = kh[(size_t)t * HID + h * D + dd]; }
        else        { eq = qe[(size_t)(t - TH) * HID + h * D + dd]; ek = ke[(size_t)(t - TH) * HID + h * D + dd]; }
        EQ[t * EPAD + dd] = eq; EK[t * EPAD + dd] = ek;
    }
    __syncthreads();

    // thread -> (ll pair, 6 t-pairs)
    const int pl = tid >> 3;         // 0..31 -> ll = 2*pl
    const int tc = tid & 7;          // t-pair group start
    const int ll = pl * 2;

    float acc[6][2][2];
#pragma unroll
    for (int s = 0; s < 6; ++s)
#pragma unroll
        for (int a = 0; a < 2; ++a)
#pragma unroll
            for (int b2 = 0; b2 < 2; ++b2) acc[s][a][b2] = 0.f;

    for (int dd = 0; dd < D; dd += 4) {
        float4 q0 = *(const float4*)&qs[ll * D + dd];
        float4 q1 = *(const float4*)&qs[(ll + 1) * D + dd];
        float4 k0 = *(const float4*)&ks[ll * D + dd];
        float4 k1 = *(const float4*)&ks[(ll + 1) * D + dd];
#pragma unroll
        for (int s = 0; s < 6; ++s) {
            int t = 2 * (tc + 8 * s);
            float4 eq0 = *(const float4*)&EQ[t * EPAD + dd];
            float4 eq1 = *(const float4*)&EQ[(t + 1) * EPAD + dd];
            float4 ek0 = *(const float4*)&EK[t * EPAD + dd];
            float4 ek1 = *(const float4*)&EK[(t + 1) * EPAD + dd];
            acc[s][0][0] += q0.x*eq0.x + q0.y*eq0.y + q0.z*eq0.z + q0.w*eq0.w
                          + k0.x*ek0.x + k0.y*ek0.y + k0.z*ek0.z + k0.w*ek0.w;
            acc[s][0][1] += q0.x*eq1.x + q0.y*eq1.y + q0.z*eq1.z + q0.w*eq1.w
                          + k0.x*ek1.x + k0.y*ek1.y + k0.z*ek1.z + k0.w*ek1.w;
            acc[s][1][0] += q1.x*eq0.x + q1.y*eq0.y + q1.z*eq0.z + q1.w*eq0.w
                          + k1.x*ek0.x + k1.y*ek0.y + k1.z*ek0.z + k1.w*ek0.w;
            acc[s][1][1] += q1.x*eq1.x + q1.y*eq1.y + q1.z*eq1.z + q1.w*eq1.w
                          + k1.x*ek1.x + k1.y*ek1.y + k1.z*ek1.z + k1.w*ek1.w;
        }
    }

    float* Pout = g_P + ((size_t)bh * L + l0) * TT;
#pragma unroll
    for (int s = 0; s < 6; ++s) {
        int t = 2 * (tc + 8 * s);
#pragma unroll
        for (int a = 0; a < 2; ++a) {
            Pout[(ll + a) * TT + t]     = acc[s][a][0];
            Pout[(ll + a) * TT + t + 1] = acc[s][a][1];
        }
    }
}

// ------------- attention: scores + gathered bias + softmax + AV + type-values
#define AT_ROWS 32
#define ATT_SMEM_FLOATS (AT_ROWS*512 + AT_ROWS*64 + AT_ROWS*TT + AT_ROWS*TT + TT*65)

__global__ __launch_bounds__(256) void attn_kernel(
    const int* __restrict__ hop, const int* __restrict__ edge,
    const float* __restrict__ vh, const float* __restrict__ ve)
{
    extern __shared__ float sm[];
    float* sc   = sm;                    // [32][512] scores -> att
    float* qs   = sc + AT_ROWS * 512;    // [32][64]
    float* Ps   = qs + AT_ROWS * 64;     // [32][96]
    float* bins = Ps + AT_ROWS * TT;     // [32][96]
    float* buf  = bins + AT_ROWS * TT;   // [96][65] staging

    const int bh = blockIdx.y;
    const int bb = bh / NH, h = bh % NH;
    const int i0 = blockIdx.x * AT_ROWS;
    const int tid = threadIdx.x;
    const float scale = 0.125f;

    {
        const float* Qp = g_Q + ((size_t)bh * L + i0) * D;
        for (int idx = tid; idx < AT_ROWS * D; idx += 256) qs[idx] = Qp[idx];
        const float* Pp = g_P + ((size_t)bh * L + i0) * TT;
        for (int idx = tid; idx < AT_ROWS * TT; idx += 256) { Ps[idx] = Pp[idx]; bins[idx] = 0.f; }
    }

    const size_t hopBase = ((size_t)bb * L + i0) * L;

    // ---- scores ----
    for (int jc = 0; jc < L; jc += 64) {
        const float* Kp = g_K + ((size_t)bh * L + jc) * D;
        for (int idx = tid; idx < 64 * D; idx += 256)
            buf[(idx >> 6) * 65 + (idx & 63)] = Kp[idx];
        __syncthreads();
        for (int p = tid; p < AT_ROWS * 64; p += 256) {
            int i = p >> 6, j = p & 63;
            float s = 0.f;
#pragma unroll
            for (int dd = 0; dd < D; ++dd) s += qs[i * D + dd] * buf[j * 65 + dd];
            int jg = jc + j;
            int hv = hop [hopBase + (size_t)i * L + jg];
            int ev = edge[hopBase + (size_t)i * L + jg];
            s += Ps[i * TT + hv] + Ps[i * TT + TH + ev];
            sc[i * 512 + jg] = s;
        }
        __syncthreads();
    }

    // ---- softmax + scatter into type bins ----
    {
        const int warp = tid >> 5, lane = tid & 31;
        for (int i = warp * 4; i < warp * 4 + 4; ++i) {
            float m = -1e30f;
            for (int j = lane; j < L; j += 32) m = fmaxf(m, sc[i * 512 + j]);
#pragma unroll
            for (int off = 16; off > 0; off >>= 1) m = fmaxf(m, __shfl_xor_sync(0xffffffffu, m, off));
            float sum = 0.f;
            for (int j = lane; j < L; j += 32) {
                float e = __expf((sc[i * 512 + j] - m) * scale);
                sc[i * 512 + j] = e;
                sum += e;
            }
#pragma unroll
            for (int off = 16; off > 0; off >>= 1) sum += __shfl_xor_sync(0xffffffffu, sum, off);
            float rinv = 1.f / sum;
            const int* hr = hop  + hopBase + (size_t)i * L;
            const int* er = edge + hopBase + (size_t)i * L;
            for (int j = lane; j < L; j += 32) {
                float a = sc[i * 512 + j] * rinv;
                sc[i * 512 + j] = a;
                atomicAdd(&bins[i * TT + hr[j]], a);
                atomicAdd(&bins[i * TT + TH + er[j]], a);
            }
        }
    }
    __syncthreads();

    // ---- AV + type-value contribution ----
    const int dd = tid & 63;
    const int ib = tid >> 6;
    float acc[8];
#pragma unroll
    for (int k2 = 0; k2 < 8; ++k2) acc[k2] = 0.f;

    for (int jc = 0; jc < L; jc += 64) {
        const float* Vp = g_V + ((size_t)bh * L + jc) * D;
        for (int idx = tid; idx < 64 * D; idx += 256)
            buf[(idx >> 6) * 65 + (idx & 63)] = Vp[idx];
        __syncthreads();
        for (int j = 0; j < 64; ++j) {
            float bvv = buf[j * 65 + dd];
#pragma unroll
            for (int k2 = 0; k2 < 8; ++k2)
                acc[k2] += sc[(ib + 4 * k2) * 512 + jc + j] * bvv;
        }
        __syncthreads();
    }

    for (int idx = tid; idx < TT * D; idx += 256) {
        int t = idx >> 6, d2 = idx & 63;
        buf[t * 65 + d2] = (t < TH) ? vh[(size_t)t * HID + h * D + d2]
                                    : ve[(size_t)(t - TH) * HID + h * D + d2];
    }
    __syncthreads();
    for (int t = 0; t < TT; ++t) {
        float bvv = buf[t * 65 + dd];
#pragma unroll
        for (int k2 = 0; k2 < 8; ++k2)
            acc[k2] += bins[(ib + 4 * k2) * TT + t] * bvv;
    }

#pragma unroll
    for (int k2 = 0; k2 < 8; ++k2) {
        int i = ib + 4 * k2;
        g_AO[((size_t)bb * L + i0 + i) * HID + h * D + dd] = acc[k2];
    }
}

// --------------------------------------------------------------------------
extern "C" void kernel_launch(void* const* d_in, const int* in_sizes, int n_in,
                              void* d_out, int out_size)
{
    const float* x   = (const float*)d_in[0];
    const float* qh  = (const float*)d_in[1];
    const float* qe  = (const float*)d_in[2];
    const float* kh  = (const float*)d_in[3];
    const float* ke  = (const float*)d_in[4];
    const float* vh  = (const float*)d_in[5];
    const float* ve  = (const float*)d_in[6];
    const int*   hop = (const int*)d_in[7];
    const int*   edg = (const int*)d_in[8];
    const float* Wq = (const float*)d_in[9];   const float* bq = (const float*)d_in[10];
    const float* Wk = (const float*)d_in[11];  const float* bk = (const float*)d_in[12];
    const float* Wv = (const float*)d_in[13];  const float* bv = (const float*)d_in[14];
    const float* Wo = (const float*)d_in[15];  const float* bo = (const float*)d_in[16];
    float* out = (float*)d_out;

    float *Qp, *Kp, *Vp, *AOp;
    cudaGetSymbolAddress((void**)&Qp,  g_Q);
    cudaGetSymbolAddress((void**)&Kp,  g_K);
    cudaGetSymbolAddress((void**)&Vp,  g_V);
    cudaGetSymbolAddress((void**)&AOp, g_AO);

    const int projSmem = (64*64*2 + TT*EPAD*2) * (int)sizeof(float);
    const int attSmem  = ATT_SMEM_FLOATS * (int)sizeof(float);
    cudaFuncSetAttribute(proj_kernel, cudaFuncAttributeMaxDynamicSharedMemorySize, projSmem);
    cudaFuncSetAttribute(attn_kernel, cudaFuncAttributeMaxDynamicSharedMemorySize, attSmem);

    dim3 gb(ROWS / GM, HID / GN);

    gemm_kernel<<<gb, 256>>>(x, Wq, bq, Qp, 1);
    gemm_kernel<<<gb, 256>>>(x, Wk, bk, Kp, 1);
    gemm_kernel<<<gb, 256>>>(x, Wv, bv, Vp, 1);
    proj_kernel<<<dim3(BH, L / 64), 256, projSmem>>>(qh, qe, kh, ke);
    attn_kernel<<<dim3(L / AT_ROWS, BH), 256, attSmem>>>(hop, edg, vh, ve);
    gemm_kernel<<<gb, 256>>>(AOp, Wo, bo, out, 0);
}

// round 6
// speedup vs baseline: 1.2349x; 1.2349x over previous
#include <cuda_runtime.h>

#define B 8
#define L 512
#define HID 768
#define NH 12
#define D 64
#define TH 32
#define TE 64
#define TT 96
#define BH (B*NH)
#define ROWS (B*L)

typedef unsigned long long ull;

__device__ __forceinline__ ull pack2(float lo, float hi) {
    ull r; asm("mov.b64 %0, {%1,%2};" : "=l"(r) : "f"(lo), "f"(hi)); return r;
}
__device__ __forceinline__ ull ffma2(ull a, ull b, ull c) {
    ull d; asm("fma.rn.f32x2 %0, %1, %2, %3;" : "=l"(d) : "l"(a), "l"(b), "l"(c)); return d;
}
__device__ __forceinline__ float2 unpack2(ull v) {
    float2 f; asm("mov.b64 {%0,%1}, %2;" : "=f"(f.x), "=f"(f.y) : "l"(v)); return f;
}

// ---------------- scratch ----------------
__device__ float g_Q[BH*L*D];
__device__ float g_K[BH*L*D];
__device__ float g_V[BH*L*D];
__device__ float g_P[BH*L*TT];
__device__ float g_AO[ROWS*HID];

// ---------------- GEMM (unchanged from passing R4) ----------------
#define GM 128
#define GN 128
#define GK 16

__global__ __launch_bounds__(256, 2) void gemm_kernel(
    const float* __restrict__ A, const float* __restrict__ W,
    const float* __restrict__ bias, float* __restrict__ Cout, int headLayout)
{
    __shared__ float As[GK][GM + 4];
    __shared__ float Bs[GK][GN];
    const int tid = threadIdx.x;
    const int tx = tid & 15, ty = tid >> 4;
    const int row0 = blockIdx.x * GM, col0 = blockIdx.y * GN;

    ull acc[8][4];
#pragma unroll
    for (int r = 0; r < 8; ++r)
#pragma unroll
        for (int c = 0; c < 4; ++c) acc[r][c] = 0ull;

    for (int k0 = 0; k0 < HID; k0 += GK) {
#pragma unroll
        for (int lidx = 0; lidx < (GM * GK) / 256; ++lidx) {
            int idx = tid + lidx * 256;
            int r = idx >> 4, kk = idx & 15;
            As[kk][r] = A[(size_t)(row0 + r) * HID + k0 + kk];
        }
#pragma unroll
        for (int lidx = 0; lidx < (GK * GN) / 256; ++lidx) {
            int idx = tid + lidx * 256;
            int kk = idx >> 7, c = idx & 127;
            Bs[kk][c] = W[(size_t)(k0 + kk) * HID + col0 + c];
        }
        __syncthreads();
#pragma unroll
        for (int kk = 0; kk < GK; ++kk) {
            float4 a0 = *(const float4*)&As[kk][ty * 8];
            float4 a1 = *(const float4*)&As[kk][ty * 8 + 4];
            float4 b0 = *(const float4*)&Bs[kk][tx * 8];
            float4 b1 = *(const float4*)&Bs[kk][tx * 8 + 4];
            ull bb[4];
            bb[0] = ((const ull*)&b0)[0]; bb[1] = ((const ull*)&b0)[1];
            bb[2] = ((const ull*)&b1)[0]; bb[3] = ((const ull*)&b1)[1];
            float a[8] = {a0.x, a0.y, a0.z, a0.w, a1.x, a1.y, a1.z, a1.w};
#pragma unroll
            for (int r = 0; r < 8; ++r) {
                ull aa = pack2(a[r], a[r]);
#pragma unroll
                for (int c = 0; c < 4; ++c) acc[r][c] = ffma2(aa, bb[c], acc[r][c]);
            }
        }
        __syncthreads();
    }

#pragma unroll
    for (int r = 0; r < 8; ++r) {
        int row = row0 + ty * 8 + r;
#pragma unroll
        for (int c = 0; c < 4; ++c) {
            float2 v2 = unpack2(acc[r][c]);
            int col = col0 + tx * 8 + c * 2;
#pragma unroll
            for (int u = 0; u < 2; ++u) {
                float v = (u ? v2.y : v2.x) + bias[col + u];
                int cc = col + u;
                if (headLayout) {
                    int bb2 = row >> 9, ll = row & 511, h = cc >> 6, dd = cc & 63;
                    Cout[(((size_t)bb2 * NH + h) * L + ll) * D + dd] = v;
                } else {
                    Cout[(size_t)row * HID + cc] = v;
                }
            }
        }
    }
}

// ---------------- proj (unchanged from passing R4) ----------------
#define EPAD 68

__global__ __launch_bounds__(256) void proj_kernel(
    const float* __restrict__ qh, const float* __restrict__ qe,
    const float* __restrict__ kh, const float* __restrict__ ke)
{
    extern __shared__ float sm[];
    float* qs = sm;
    float* ks = qs + 64 * 64;
    float* EQ = ks + 64 * 64;
    float* EK = EQ + TT * EPAD;

    const int bh = blockIdx.x;
    const int h  = bh % NH;
    const int l0 = blockIdx.y * 64;
    const int tid = threadIdx.x;

    const float* Qp = g_Q + ((size_t)bh * L + l0) * D;
    const float* Kp = g_K + ((size_t)bh * L + l0) * D;
    for (int idx = tid; idx < 64 * D; idx += 256) { qs[idx] = Qp[idx]; ks[idx] = Kp[idx]; }
    for (int idx = tid; idx < TT * D; idx += 256) {
        int t = idx >> 6, dd = idx & 63;
        float eq, ek;
        if (t < TH) { eq = qh[(size_t)t * HID + h * D + dd]; ek = kh[(size_t)t * HID + h * D + dd]; }
        else        { eq = qe[(size_t)(t - TH) * HID + h * D + dd]; ek = ke[(size_t)(t - TH) * HID + h * D + dd]; }
        EQ[t * EPAD + dd] = eq; EK[t * EPAD + dd] = ek;
    }
    __syncthreads();

    const int pl = tid >> 3;
    const int tc = tid & 7;
    const int ll = pl * 2;

    float acc[6][2][2];
#pragma unroll
    for (int s = 0; s < 6; ++s)
#pragma unroll
        for (int a = 0; a < 2; ++a)
#pragma unroll
            for (int b2 = 0; b2 < 2; ++b2) acc[s][a][b2] = 0.f;

    for (int dd = 0; dd < D; dd += 4) {
        float4 q0 = *(const float4*)&qs[ll * D + dd];
        float4 q1 = *(const float4*)&qs[(ll + 1) * D + dd];
        float4 k0 = *(const float4*)&ks[ll * D + dd];
        float4 k1 = *(const float4*)&ks[(ll + 1) * D + dd];
#pragma unroll
        for (int s = 0; s < 6; ++s) {
            int t = 2 * (tc + 8 * s);
            float4 eq0 = *(const float4*)&EQ[t * EPAD + dd];
            float4 eq1 = *(const float4*)&EQ[(t + 1) * EPAD + dd];
            float4 ek0 = *(const float4*)&EK[t * EPAD + dd];
            float4 ek1 = *(const float4*)&EK[(t + 1) * EPAD + dd];
            acc[s][0][0] += q0.x*eq0.x + q0.y*eq0.y + q0.z*eq0.z + q0.w*eq0.w
                          + k0.x*ek0.x + k0.y*ek0.y + k0.z*ek0.z + k0.w*ek0.w;
            acc[s][0][1] += q0.x*eq1.x + q0.y*eq1.y + q0.z*eq1.z + q0.w*eq1.w
                          + k0.x*ek1.x + k0.y*ek1.y + k0.z*ek1.z + k0.w*ek1.w;
            acc[s][1][0] += q1.x*eq0.x + q1.y*eq0.y + q1.z*eq0.z + q1.w*eq0.w
                          + k1.x*ek0.x + k1.y*ek0.y + k1.z*ek0.z + k1.w*ek0.w;
            acc[s][1][1] += q1.x*eq1.x + q1.y*eq1.y + q1.z*eq1.z + q1.w*eq1.w
                          + k1.x*ek1.x + k1.y*ek1.y + k1.z*ek1.z + k1.w*ek1.w;
        }
    }

    float* Pout = g_P + ((size_t)bh * L + l0) * TT;
#pragma unroll
    for (int s = 0; s < 6; ++s) {
        int t = 2 * (tc + 8 * s);
#pragma unroll
        for (int a = 0; a < 2; ++a) {
            Pout[(ll + a) * TT + t]     = acc[s][a][0];
            Pout[(ll + a) * TT + t + 1] = acc[s][a][1];
        }
    }
}

// ---------------- attention: register-tiled rewrite ----------------
#define AT_ROWS 32
#define SCS 516              // sc row stride (pad vs 512)
#define KSTR 132             // transposed K stage stride (4-aligned)
#define VSTR 68              // V / VE stage stride (4-aligned)
#define BUF_FLOATS (128*VSTR)   // 8704 >= 64*KSTR(8448)
#define ATT_SMEM_FLOATS (AT_ROWS*SCS + AT_ROWS*64 + AT_ROWS*TT + AT_ROWS*TT + BUF_FLOATS)

__global__ __launch_bounds__(256) void attn_kernel(
    const int* __restrict__ hop, const int* __restrict__ edge,
    const float* __restrict__ vh, const float* __restrict__ ve)
{
    extern __shared__ float sm[];
    float* sc   = sm;                      // [32][516]
    float* qs   = sc + AT_ROWS * SCS;      // [32][64]
    float* Ps   = qs + AT_ROWS * 64;       // [32][96]
    float* bins = Ps + AT_ROWS * TT;       // [32][96]
    float* buf  = bins + AT_ROWS * TT;     // staging

    const int bh = blockIdx.y;
    const int bb = bh / NH, h = bh % NH;
    const int i0 = blockIdx.x * AT_ROWS;
    const int tid = threadIdx.x;
    const float scale = 0.125f;

    // ---- load Q rows, bias table, zero bins ----
    {
        const float* Qp = g_Q + ((size_t)bh * L + i0) * D;
        for (int idx = tid; idx < AT_ROWS * D; idx += 256) qs[idx] = Qp[idx];
        const float* Pp = g_P + ((size_t)bh * L + i0) * TT;
        for (int idx = tid; idx < AT_ROWS * TT; idx += 256) { Ps[idx] = Pp[idx]; bins[idx] = 0.f; }
    }

    const size_t hopBase = ((size_t)bb * L + i0) * L;

    // ================= scores: S = Q K^T + gathered bias =================
    const int jg = tid & 31;       // j-group: 4 j's
    const int ig = tid >> 5;       // i-group: 4 i's
    const int j0 = jg * 4;
    const int ib4 = ig * 4;

    for (int jc = 0; jc < L; jc += 128) {
        // stage K chunk transposed: buf[dd][j'] (stride KSTR)
        const float* Kp = g_K + ((size_t)bh * L + jc) * D;
        for (int idx4 = tid; idx4 < 2048; idx4 += 256) {
            int jj = idx4 >> 4, dd4 = (idx4 & 15) << 2;
            float4 kv = *(const float4*)&Kp[(size_t)jj * D + dd4];
            buf[(dd4 + 0) * KSTR + jj] = kv.x;
            buf[(dd4 + 1) * KSTR + jj] = kv.y;
            buf[(dd4 + 2) * KSTR + jj] = kv.z;
            buf[(dd4 + 3) * KSTR + jj] = kv.w;
        }
        __syncthreads();

        ull acc[4][2];
#pragma unroll
        for (int r = 0; r < 4; ++r) { acc[r][0] = 0ull; acc[r][1] = 0ull; }

        for (int dd = 0; dd < D; ++dd) {
            float4 kj = *(const float4*)&buf[dd * KSTR + j0];
            ull k01 = ((const ull*)&kj)[0];
            ull k23 = ((const ull*)&kj)[1];
#pragma unroll
            for (int r = 0; r < 4; ++r) {
                float qv = qs[(ib4 + r) * D + dd];   // warp-broadcast
                ull qq = pack2(qv, qv);
                acc[r][0] = ffma2(qq, k01, acc[r][0]);
                acc[r][1] = ffma2(qq, k23, acc[r][1]);
            }
        }

        // add gathered bias, store raw scores
#pragma unroll
        for (int r = 0; r < 4; ++r) {
            int i = ib4 + r;
            const int4 hp = *(const int4*)&hop [hopBase + (size_t)i * L + jc + j0];
            const int4 ep = *(const int4*)&edge[hopBase + (size_t)i * L + jc + j0];
            float2 a0 = unpack2(acc[r][0]);
            float2 a1 = unpack2(acc[r][1]);
            const float* prow = Ps + i * TT;
            float* srow = sc + i * SCS + jc + j0;
            srow[0] = a0.x + prow[hp.x] + prow[TH + ep.x];
            srow[1] = a0.y + prow[hp.y] + prow[TH + ep.y];
            srow[2] = a1.x + prow[hp.z] + prow[TH + ep.z];
            srow[3] = a1.y + prow[hp.w] + prow[TH + ep.w];
        }
        __syncthreads();
    }

    // ================= softmax + scatter into type bins =================
    {
        const int warp = tid >> 5, lane = tid & 31;
        for (int i = warp * 4; i < warp * 4 + 4; ++i) {
            float* srow = sc + i * SCS;
            float m = -1e30f;
            for (int j = lane; j < L; j += 32) m = fmaxf(m, srow[j]);
#pragma unroll
            for (int off = 16; off > 0; off >>= 1) m = fmaxf(m, __shfl_xor_sync(0xffffffffu, m, off));
            float sum = 0.f;
            for (int j = lane; j < L; j += 32) {
                float e = __expf((srow[j] - m) * scale);
                srow[j] = e;
                sum += e;
            }
#pragma unroll
            for (int off = 16; off > 0; off >>= 1) sum += __shfl_xor_sync(0xffffffffu, sum, off);
            float rinv = 1.f / sum;
            const int* hr = hop  + hopBase + (size_t)i * L;
            const int* er = edge + hopBase + (size_t)i * L;
            for (int j = lane; j < L; j += 32) {
                float a = srow[j] * rinv;
                srow[j] = a;
                atomicAdd(&bins[i * TT + hr[j]], a);
                atomicAdd(&bins[i * TT + TH + er[j]], a);
            }
        }
    }
    __syncthreads();

    // ================= AV + type-value contribution =================
    const int g   = tid >> 7;        // j-parity group
    const int t2  = tid & 127;
    const int ig2 = t2 >> 4;         // i = 4*ig2
    const int dg  = t2 & 15;         // d0 = 4*dg
    const int i4  = ig2 * 4;
    const int d0  = dg * 4;

    ull oa[4][2];
#pragma unroll
    for (int r = 0; r < 4; ++r) { oa[r][0] = 0ull; oa[r][1] = 0ull; }

    for (int jc = 0; jc < L; jc += 128) {
        // stage V chunk j-major: buf[j'][dd] (stride VSTR)
        const float* Vp = g_V + ((size_t)bh * L + jc) * D;
        for (int idx4 = tid; idx4 < 2048; idx4 += 256) {
            int jj = idx4 >> 4, dd4 = (idx4 & 15) << 2;
            *(float4*)&buf[jj * VSTR + dd4] = *(const float4*)&Vp[(size_t)jj * D + dd4];
        }
        __syncthreads();

        for (int jj = g; jj < 128; jj += 2) {
            float4 vv = *(const float4*)&buf[jj * VSTR + d0];
            ull v01 = ((const ull*)&vv)[0];
            ull v23 = ((const ull*)&vv)[1];
#pragma unroll
            for (int r = 0; r < 4; ++r) {
                float av = sc[(i4 + r) * SCS + jc + jj];
                ull aa = pack2(av, av);
                oa[r][0] = ffma2(aa, v01, oa[r][0]);
                oa[r][1] = ffma2(aa, v23, oa[r][1]);
            }
        }
        __syncthreads();
    }

    // stage type-value embeddings: buf[t][dd]
    for (int idx = tid; idx < TT * D; idx += 256) {
        int t = idx >> 6, d2 = idx & 63;
        buf[t * VSTR + d2] = (t < TH) ? vh[(size_t)t * HID + h * D + d2]
                                      : ve[(size_t)(t - TH) * HID + h * D + d2];
    }
    __syncthreads();

    // bins x VE: group g covers t in [48g, 48g+48)
    for (int t = 48 * g; t < 48 * g + 48; ++t) {
        float4 vv = *(const float4*)&buf[t * VSTR + d0];
        ull v01 = ((const ull*)&vv)[0];
        ull v23 = ((const ull*)&vv)[1];
#pragma unroll
        for (int r = 0; r < 4; ++r) {
            float bv = bins[(i4 + r) * TT + t];
            ull aa = pack2(bv, bv);
            oa[r][0] = ffma2(aa, v01, oa[r][0]);
            oa[r][1] = ffma2(aa, v23, oa[r][1]);
        }
    }
    __syncthreads();

    // reduce the two j-parity partials and write out
    if (g == 1) {
#pragma unroll
        for (int r = 0; r < 4; ++r) {
            int i = i4 + r;
            float2 x0 = unpack2(oa[r][0]);
            float2 x1 = unpack2(oa[r][1]);
            *(float4*)&buf[i * VSTR + d0] = make_float4(x0.x, x0.y, x1.x, x1.y);
        }
    }
    __syncthreads();
    if (g == 0) {
#pragma unroll
        for (int r = 0; r < 4; ++r) {
            int i = i4 + r;
            float4 ov = *(const float4*)&buf[i * VSTR + d0];
            float2 x0 = unpack2(oa[r][0]);
            float2 x1 = unpack2(oa[r][1]);
            float4 res = make_float4(x0.x + ov.x, x0.y + ov.y, x1.x + ov.z, x1.y + ov.w);
            *(float4*)&g_AO[((size_t)bb * L + i0 + i) * HID + h * D + d0] = res;
        }
    }
}

// --------------------------------------------------------------------------
extern "C" void kernel_launch(void* const* d_in, const int* in_sizes, int n_in,
                              void* d_out, int out_size)
{
    const float* x   = (const float*)d_in[0];
    const float* qh  = (const float*)d_in[1];
    const float* qe  = (const float*)d_in[2];
    const float* kh  = (const float*)d_in[3];
    const float* ke  = (const float*)d_in[4];
    const float* vh  = (const float*)d_in[5];
    const float* ve  = (const float*)d_in[6];
    const int*   hop = (const int*)d_in[7];
    const int*   edg = (const int*)d_in[8];
    const float* Wq = (const float*)d_in[9];   const float* bq = (const float*)d_in[10];
    const float* Wk = (const float*)d_in[11];  const float* bk = (const float*)d_in[12];
    const float* Wv = (const float*)d_in[13];  const float* bv = (const float*)d_in[14];
    const float* Wo = (const float*)d_in[15];  const float* bo = (const float*)d_in[16];
    float* out = (float*)d_out;

    float *Qp, *Kp, *Vp, *AOp;
    cudaGetSymbolAddress((void**)&Qp,  g_Q);
    cudaGetSymbolAddress((void**)&Kp,  g_K);
    cudaGetSymbolAddress((void**)&Vp,  g_V);
    cudaGetSymbolAddress((void**)&AOp, g_AO);

    const int projSmem = (64*64*2 + TT*EPAD*2) * (int)sizeof(float);
    const int attSmem  = ATT_SMEM_FLOATS * (int)sizeof(float);
    cudaFuncSetAttribute(proj_kernel, cudaFuncAttributeMaxDynamicSharedMemorySize, projSmem);
    cudaFuncSetAttribute(attn_kernel, cudaFuncAttributeMaxDynamicSharedMemorySize, attSmem);

    dim3 gb(ROWS / GM, HID / GN);

    gemm_kernel<<<gb, 256>>>(x, Wq, bq, Qp, 1);
    gemm_kernel<<<gb, 256>>>(x, Wk, bk, Kp, 1);
    gemm_kernel<<<gb, 256>>>(x, Wv, bv, Vp, 1);
    proj_kernel<<<dim3(BH, L / 64), 256, projSmem>>>(qh, qe, kh, ke);
    attn_kernel<<<dim3(L / AT_ROWS, BH), 256, attSmem>>>(hop, edg, vh, ve);
    gemm_kernel<<<gb, 256>>>(AOp, Wo, bo, out, 0);
}

// round 8
// speedup vs baseline: 1.5843x; 1.2830x over previous
#include <cuda_runtime.h>
#include <cstdint>

#define B 8
#define L 512
#define HID 768
#define NH 12
#define D 64
#define TH 32
#define TE 64
#define TT 96
#define BH (B*NH)
#define ROWS (B*L)

typedef unsigned long long ull;

__device__ __forceinline__ ull pack2(float lo, float hi) {
    ull r; asm("mov.b64 %0, {%1,%2};" : "=l"(r) : "f"(lo), "f"(hi)); return r;
}
__device__ __forceinline__ ull ffma2(ull a, ull b, ull c) {
    ull d; asm("fma.rn.f32x2 %0, %1, %2, %3;" : "=l"(d) : "l"(a), "l"(b), "l"(c)); return d;
}
__device__ __forceinline__ float2 unpack2(ull v) {
    float2 f; asm("mov.b64 {%0,%1}, %2;" : "=f"(f.x), "=f"(f.y) : "l"(v)); return f;
}
__device__ __forceinline__ uint32_t f2tf32(float x) {
    uint32_t u; asm("cvt.rna.tf32.f32 %0, %1;" : "=r"(u) : "f"(x)); return u;
}
__device__ __forceinline__ void mma_tf32(float* d, const uint32_t* a, const uint32_t* b) {
    asm volatile(
        "mma.sync.aligned.m16n8k8.row.col.f32.tf32.tf32.f32 "
        "{%0,%1,%2,%3}, {%4,%5,%6,%7}, {%8,%9}, {%0,%1,%2,%3};"
        : "+f"(d[0]), "+f"(d[1]), "+f"(d[2]), "+f"(d[3])
        : "r"(a[0]), "r"(a[1]), "r"(a[2]), "r"(a[3]), "r"(b[0]), "r"(b[1]));
}

// ---------------- scratch ----------------
__device__ float g_Q[BH*L*D];
__device__ float g_K[BH*L*D];
__device__ float g_V[BH*L*D];
__device__ float g_P[BH*L*TT];
__device__ float g_AO[ROWS*HID];
__device__ float g_WT[HID*HID];

// ---------------- W transpose: WT[n][k] = W[k][n] ----------------
__global__ __launch_bounds__(256) void transpose_kernel(
    const float* __restrict__ Wsrc, float* __restrict__ Wdst)
{
    __shared__ float t[32][33];
    int x  = blockIdx.x * 32 + threadIdx.x;
    int y0 = blockIdx.y * 32 + threadIdx.y;
#pragma unroll
    for (int dy = 0; dy < 32; dy += 8)
        t[threadIdx.y + dy][threadIdx.x] = Wsrc[(size_t)(y0 + dy) * HID + x];
    __syncthreads();
    int xo  = blockIdx.y * 32 + threadIdx.x;
    int yo0 = blockIdx.x * 32 + threadIdx.y;
#pragma unroll
    for (int dy = 0; dy < 32; dy += 8)
        Wdst[(size_t)(yo0 + dy) * HID + xo] = t[threadIdx.x][threadIdx.y + dy];
}

// ---------------- tf32 mma.sync GEMM: C = A[4096,768] @ W + bias -----------
// A row-major, B = WT rows (K contiguous per output col) -> mma row.col form.
#define KC 32
#define KCP 36          // row stride: (36g + t) mod 32 = 4g+t -> conflict-free frags

__global__ __launch_bounds__(256, 2) void gemm_mma_kernel(
    const float* __restrict__ A, const float* __restrict__ WT,
    const float* __restrict__ bias, float* __restrict__ Cout, int headLayout)
{
    __shared__ float As[128 * KCP];
    __shared__ float Bs[128 * KCP];

    const int tid = threadIdx.x;
    const int wid = tid >> 5, lane = tid & 31;
    const int g = lane >> 2, t = lane & 3;
    const int warp_m = wid & 3;        // 4 warps along M, 32 rows each
    const int warp_n = wid >> 2;       // 2 warps along N, 64 cols each
    const int row0 = blockIdx.x * 128, col0 = blockIdx.y * 128;

    float acc[2][8][4];
#pragma unroll
    for (int mf = 0; mf < 2; ++mf)
#pragma unroll
        for (int nf = 0; nf < 8; ++nf)
#pragma unroll
            for (int c = 0; c < 4; ++c) acc[mf][nf][c] = 0.f;

    const int mbase = warp_m * 32;
    const int nbase = warp_n * 64;

    for (int k0 = 0; k0 < HID; k0 += KC) {
        // stage A and B chunks (tf32-rounded), 128 rows x 32 k each
#pragma unroll
        for (int it = 0; it < 4; ++it) {
            int idx = tid + it * 256;       // 0..1023
            int r = idx >> 3, v = (idx & 7) << 2;
            float4 a = *(const float4*)&A[(size_t)(row0 + r) * HID + k0 + v];
            float4 b = *(const float4*)&WT[(size_t)(col0 + r) * HID + k0 + v];
            float* da = &As[r * KCP + v];
            da[0] = __uint_as_float(f2tf32(a.x)); da[1] = __uint_as_float(f2tf32(a.y));
            da[2] = __uint_as_float(f2tf32(a.z)); da[3] = __uint_as_float(f2tf32(a.w));
            float* db = &Bs[r * KCP + v];
            db[0] = __uint_as_float(f2tf32(b.x)); db[1] = __uint_as_float(f2tf32(b.y));
            db[2] = __uint_as_float(f2tf32(b.z)); db[3] = __uint_as_float(f2tf32(b.w));
        }
        __syncthreads();

#pragma unroll
        for (int kk = 0; kk < KC; kk += 8) {
            uint32_t bfr[8][2];
#pragma unroll
            for (int nf = 0; nf < 8; ++nf) {
                const float* bp = &Bs[(nbase + nf * 8 + g) * KCP + kk + t];
                bfr[nf][0] = __float_as_uint(bp[0]);
                bfr[nf][1] = __float_as_uint(bp[4]);
            }
            uint32_t afr[2][4];
#pragma unroll
            for (int mf = 0; mf < 2; ++mf) {
                const float* ap = &As[(mbase + mf * 16 + g) * KCP + kk + t];
                afr[mf][0] = __float_as_uint(ap[0]);
                afr[mf][1] = __float_as_uint(ap[8 * KCP]);
                afr[mf][2] = __float_as_uint(ap[4]);
                afr[mf][3] = __float_as_uint(ap[8 * KCP + 4]);
            }
#pragma unroll
            for (int mf = 0; mf < 2; ++mf)
#pragma unroll
                for (int nf = 0; nf < 8; ++nf)
                    mma_tf32(acc[mf][nf], afr[mf], bfr[nf]);
        }
        __syncthreads();
    }

    // epilogue: c0:(g,2t) c1:(g,2t+1) c2:(g+8,2t) c3:(g+8,2t+1)
#pragma unroll
    for (int mf = 0; mf < 2; ++mf) {
#pragma unroll
        for (int nf = 0; nf < 8; ++nf) {
            int row_a = row0 + mbase + mf * 16 + g;
            int col_a = col0 + nbase + nf * 8 + 2 * t;
#pragma unroll
            for (int half = 0; half < 2; ++half) {
                int row = row_a + half * 8;
                float2 v;
                v.x = acc[mf][nf][2 * half]     + bias[col_a];
                v.y = acc[mf][nf][2 * half + 1] + bias[col_a + 1];
                if (headLayout) {
                    int bb2 = row >> 9, ll = row & 511, hh = col_a >> 6, dd = col_a & 63;
                    *(float2*)&Cout[(((size_t)bb2 * NH + hh) * L + ll) * D + dd] = v;
                } else {
                    *(float2*)&Cout[(size_t)row * HID + col_a] = v;
                }
            }
        }
    }
}

// ---------------- SIMT GEMM (final Wo GEMM, fp32-exact) ----------------
#define GM 128
#define GN 128
#define GK 16

__global__ __launch_bounds__(256, 2) void gemm_kernel(
    const float* __restrict__ A, const float* __restrict__ W,
    const float* __restrict__ bias, float* __restrict__ Cout, int headLayout)
{
    __shared__ float As[GK][GM + 4];
    __shared__ float Bs[GK][GN];
    const int tid = threadIdx.x;
    const int tx = tid & 15, ty = tid >> 4;
    const int row0 = blockIdx.x * GM, col0 = blockIdx.y * GN;

    ull acc[8][4];
#pragma unroll
    for (int r = 0; r < 8; ++r)
#pragma unroll
        for (int c = 0; c < 4; ++c) acc[r][c] = 0ull;

    for (int k0 = 0; k0 < HID; k0 += GK) {
#pragma unroll
        for (int lidx = 0; lidx < (GM * GK) / 256; ++lidx) {
            int idx = tid + lidx * 256;
            int r = idx >> 4, kk = idx & 15;
            As[kk][r] = A[(size_t)(row0 + r) * HID + k0 + kk];
        }
#pragma unroll
        for (int lidx = 0; lidx < (GK * GN) / 256; ++lidx) {
            int idx = tid + lidx * 256;
            int kk = idx >> 7, c = idx & 127;
            Bs[kk][c] = W[(size_t)(k0 + kk) * HID + col0 + c];
        }
        __syncthreads();
#pragma unroll
        for (int kk = 0; kk < GK; ++kk) {
            float4 a0 = *(const float4*)&As[kk][ty * 8];
            float4 a1 = *(const float4*)&As[kk][ty * 8 + 4];
            float4 b0 = *(const float4*)&Bs[kk][tx * 8];
            float4 b1 = *(const float4*)&Bs[kk][tx * 8 + 4];
            ull bb[4];
            bb[0] = ((const ull*)&b0)[0]; bb[1] = ((const ull*)&b0)[1];
            bb[2] = ((const ull*)&b1)[0]; bb[3] = ((const ull*)&b1)[1];
            float a[8] = {a0.x, a0.y, a0.z, a0.w, a1.x, a1.y, a1.z, a1.w};
#pragma unroll
            for (int r = 0; r < 8; ++r) {
                ull aa = pack2(a[r], a[r]);
#pragma unroll
                for (int c = 0; c < 4; ++c) acc[r][c] = ffma2(aa, bb[c], acc[r][c]);
            }
        }
        __syncthreads();
    }

#pragma unroll
    for (int r = 0; r < 8; ++r) {
        int row = row0 + ty * 8 + r;
#pragma unroll
        for (int c = 0; c < 4; ++c) {
            float2 v2 = unpack2(acc[r][c]);
            int col = col0 + tx * 8 + c * 2;
#pragma unroll
            for (int u = 0; u < 2; ++u) {
                float v = (u ? v2.y : v2.x) + bias[col + u];
                int cc = col + u;
                if (headLayout) {
                    int bb2 = row >> 9, ll = row & 511, h = cc >> 6, dd = cc & 63;
                    Cout[(((size_t)bb2 * NH + h) * L + ll) * D + dd] = v;
                } else {
                    Cout[(size_t)row * HID + cc] = v;
                }
            }
        }
    }
}

// ---------------- proj (unchanged) ----------------
#define EPAD 68

__global__ __launch_bounds__(256) void proj_kernel(
    const float* __restrict__ qh, const float* __restrict__ qe,
    const float* __restrict__ kh, const float* __restrict__ ke)
{
    extern __shared__ float sm[];
    float* qs = sm;
    float* ks = qs + 64 * 64;
    float* EQ = ks + 64 * 64;
    float* EK = EQ + TT * EPAD;

    const int bh = blockIdx.x;
    const int h  = bh % NH;
    const int l0 = blockIdx.y * 64;
    const int tid = threadIdx.x;

    const float* Qp = g_Q + ((size_t)bh * L + l0) * D;
    const float* Kp = g_K + ((size_t)bh * L + l0) * D;
    for (int idx = tid; idx < 64 * D; idx += 256) { qs[idx] = Qp[idx]; ks[idx] = Kp[idx]; }
    for (int idx = tid; idx < TT * D; idx += 256) {
        int t = idx >> 6, dd = idx & 63;
        float eq, ek;
        if (t < TH) { eq = qh[(size_t)t * HID + h * D + dd]; ek = kh[(size_t)t * HID + h * D + dd]; }
        else        { eq = qe[(size_t)(t - TH) * HID + h * D + dd]; ek = ke[(size_t)(t - TH) * HID + h * D + dd]; }
        EQ[t * EPAD + dd] = eq; EK[t * EPAD + dd] = ek;
    }
    __syncthreads();

    const int pl = tid >> 3;
    const int tc = tid & 7;
    const int ll = pl * 2;

    float acc[6][2][2];
#pragma unroll
    for (int s = 0; s < 6; ++s)
#pragma unroll
        for (int a = 0; a < 2; ++a)
#pragma unroll
            for (int b2 = 0; b2 < 2; ++b2) acc[s][a][b2] = 0.f;

    for (int dd = 0; dd < D; dd += 4) {
        float4 q0 = *(const float4*)&qs[ll * D + dd];
        float4 q1 = *(const float4*)&qs[(ll + 1) * D + dd];
        float4 k0 = *(const float4*)&ks[ll * D + dd];
        float4 k1 = *(const float4*)&ks[(ll + 1) * D + dd];
#pragma unroll
        for (int s = 0; s < 6; ++s) {
            int t = 2 * (tc + 8 * s);
            float4 eq0 = *(const float4*)&EQ[t * EPAD + dd];
            float4 eq1 = *(const float4*)&EQ[(t + 1) * EPAD + dd];
            float4 ek0 = *(const float4*)&EK[t * EPAD + dd];
            float4 ek1 = *(const float4*)&EK[(t + 1) * EPAD + dd];
            acc[s][0][0] += q0.x*eq0.x + q0.y*eq0.y + q0.z*eq0.z + q0.w*eq0.w
                          + k0.x*ek0.x + k0.y*ek0.y + k0.z*ek0.z + k0.w*ek0.w;
            acc[s][0][1] += q0.x*eq1.x + q0.y*eq1.y + q0.z*eq1.z + q0.w*eq1.w
                          + k0.x*ek1.x + k0.y*ek1.y + k0.z*ek1.z + k0.w*ek1.w;
            acc[s][1][0] += q1.x*eq0.x + q1.y*eq0.y + q1.z*eq0.z + q1.w*eq0.w
                          + k1.x*ek0.x + k1.y*ek0.y + k1.z*ek0.z + k1.w*ek0.w;
            acc[s][1][1] += q1.x*eq1.x + q1.y*eq1.y + q1.z*eq1.z + q1.w*eq1.w
                          + k1.x*ek1.x + k1.y*ek1.y + k1.z*ek1.z + k1.w*ek1.w;
        }
    }

    float* Pout = g_P + ((size_t)bh * L + l0) * TT;
#pragma unroll
    for (int s = 0; s < 6; ++s) {
        int t = 2 * (tc + 8 * s);
#pragma unroll
        for (int a = 0; a < 2; ++a) {
            Pout[(ll + a) * TT + t]     = acc[s][a][0];
            Pout[(ll + a) * TT + t + 1] = acc[s][a][1];
        }
    }
}

// ---------------- attention (unchanged from R6 win) ----------------
#define AT_ROWS 32
#define SCS 516
#define KSTR 132
#define VSTR 68
#define BUF_FLOATS (128*VSTR)
#define ATT_SMEM_FLOATS (AT_ROWS*SCS + AT_ROWS*64 + AT_ROWS*TT + AT_ROWS*TT + BUF_FLOATS)

__global__ __launch_bounds__(256) void attn_kernel(
    const int* __restrict__ hop, const int* __restrict__ edge,
    const float* __restrict__ vh, const float* __restrict__ ve)
{
    extern __shared__ float sm[];
    float* sc   = sm;
    float* qs   = sc + AT_ROWS * SCS;
    float* Ps   = qs + AT_ROWS * 64;
    float* bins = Ps + AT_ROWS * TT;
    float* buf  = bins + AT_ROWS * TT;

    const int bh = blockIdx.y;
    const int bb = bh / NH, h = bh % NH;
    const int i0 = blockIdx.x * AT_ROWS;
    const int tid = threadIdx.x;
    const float scale = 0.125f;

    {
        const float* Qp = g_Q + ((size_t)bh * L + i0) * D;
        for (int idx = tid; idx < AT_ROWS * D; idx += 256) qs[idx] = Qp[idx];
        const float* Pp = g_P + ((size_t)bh * L + i0) * TT;
        for (int idx = tid; idx < AT_ROWS * TT; idx += 256) { Ps[idx] = Pp[idx]; bins[idx] = 0.f; }
    }

    const size_t hopBase = ((size_t)bb * L + i0) * L;

    const int jg = tid & 31;
    const int ig = tid >> 5;
    const int j0 = jg * 4;
    const int ib4 = ig * 4;

    for (int jc = 0; jc < L; jc += 128) {
        const float* Kp = g_K + ((size_t)bh * L + jc) * D;
        for (int idx4 = tid; idx4 < 2048; idx4 += 256) {
            int jj = idx4 >> 4, dd4 = (idx4 & 15) << 2;
            float4 kv = *(const float4*)&Kp[(size_t)jj * D + dd4];
            buf[(dd4 + 0) * KSTR + jj] = kv.x;
            buf[(dd4 + 1) * KSTR + jj] = kv.y;
            buf[(dd4 + 2) * KSTR + jj] = kv.z;
            buf[(dd4 + 3) * KSTR + jj] = kv.w;
        }
        __syncthreads();

        ull acc[4][2];
#pragma unroll
        for (int r = 0; r < 4; ++r) { acc[r][0] = 0ull; acc[r][1] = 0ull; }

        for (int dd = 0; dd < D; ++dd) {
            float4 kj = *(const float4*)&buf[dd * KSTR + j0];
            ull k01 = ((const ull*)&kj)[0];
            ull k23 = ((const ull*)&kj)[1];
#pragma unroll
            for (int r = 0; r < 4; ++r) {
                float qv = qs[(ib4 + r) * D + dd];
                ull qq = pack2(qv, qv);
                acc[r][0] = ffma2(qq, k01, acc[r][0]);
                acc[r][1] = ffma2(qq, k23, acc[r][1]);
            }
        }

#pragma unroll
        for (int r = 0; r < 4; ++r) {
            int i = ib4 + r;
            const int4 hp = *(const int4*)&hop [hopBase + (size_t)i * L + jc + j0];
            const int4 ep = *(const int4*)&edge[hopBase + (size_t)i * L + jc + j0];
            float2 a0 = unpack2(acc[r][0]);
            float2 a1 = unpack2(acc[r][1]);
            const float* prow = Ps + i * TT;
            float* srow = sc + i * SCS + jc + j0;
            srow[0] = a0.x + prow[hp.x] + prow[TH + ep.x];
            srow[1] = a0.y + prow[hp.y] + prow[TH + ep.y];
            srow[2] = a1.x + prow[hp.z] + prow[TH + ep.z];
            srow[3] = a1.y + prow[hp.w] + prow[TH + ep.w];
        }
        __syncthreads();
    }

    {
        const int warp = tid >> 5, lane = tid & 31;
        for (int i = warp * 4; i < warp * 4 + 4; ++i) {
            float* srow = sc + i * SCS;
            float m = -1e30f;
            for (int j = lane; j < L; j += 32) m = fmaxf(m, srow[j]);
#pragma unroll
            for (int off = 16; off > 0; off >>= 1) m = fmaxf(m, __shfl_xor_sync(0xffffffffu, m, off));
            float sum = 0.f;
            for (int j = lane; j < L; j += 32) {
                float e = __expf((srow[j] - m) * scale);
                srow[j] = e;
                sum += e;
            }
#pragma unroll
            for (int off = 16; off > 0; off >>= 1) sum += __shfl_xor_sync(0xffffffffu, sum, off);
            float rinv = 1.f / sum;
            const int* hr = hop  + hopBase + (size_t)i * L;
            const int* er = edge + hopBase + (size_t)i * L;
            for (int j = lane; j < L; j += 32) {
                float a = srow[j] * rinv;
                srow[j] = a;
                atomicAdd(&bins[i * TT + hr[j]], a);
                atomicAdd(&bins[i * TT + TH + er[j]], a);
            }
        }
    }
    __syncthreads();

    const int g   = tid >> 7;
    const int t2  = tid & 127;
    const int ig2 = t2 >> 4;
    const int dg  = t2 & 15;
    const int i4  = ig2 * 4;
    const int d0  = dg * 4;

    ull oa[4][2];
#pragma unroll
    for (int r = 0; r < 4; ++r) { oa[r][0] = 0ull; oa[r][1] = 0ull; }

    for (int jc = 0; jc < L; jc += 128) {
        const float* Vp = g_V + ((size_t)bh * L + jc) * D;
        for (int idx4 = tid; idx4 < 2048; idx4 += 256) {
            int jj = idx4 >> 4, dd4 = (idx4 & 15) << 2;
            *(float4*)&buf[jj * VSTR + dd4] = *(const float4*)&Vp[(size_t)jj * D + dd4];
        }
        __syncthreads();

        for (int jj = g; jj < 128; jj += 2) {
            float4 vv = *(const float4*)&buf[jj * VSTR + d0];
            ull v01 = ((const ull*)&vv)[0];
            ull v23 = ((const ull*)&vv)[1];
#pragma unroll
            for (int r = 0; r < 4; ++r) {
                float av = sc[(i4 + r) * SCS + jc + jj];
                ull aa = pack2(av, av);
                oa[r][0] = ffma2(aa, v01, oa[r][0]);
                oa[r][1] = ffma2(aa, v23, oa[r][1]);
            }
        }
        __syncthreads();
    }

    for (int idx = tid; idx < TT * D; idx += 256) {
        int t = idx >> 6, d2 = idx & 63;
        buf[t * VSTR + d2] = (t < TH) ? vh[(size_t)t * HID + h * D + d2]
                                      : ve[(size_t)(t - TH) * HID + h * D + d2];
    }
    __syncthreads();

    for (int t = 48 * g; t < 48 * g + 48; ++t) {
        float4 vv = *(const float4*)&buf[t * VSTR + d0];
        ull v01 = ((const ull*)&vv)[0];
        ull v23 = ((const ull*)&vv)[1];
#pragma unroll
        for (int r = 0; r < 4; ++r) {
            float bv = bins[(i4 + r) * TT + t];
            ull aa = pack2(bv, bv);
            oa[r][0] = ffma2(aa, v01, oa[r][0]);
            oa[r][1] = ffma2(aa, v23, oa[r][1]);
        }
    }
    __syncthreads();

    if (g == 1) {
#pragma unroll
        for (int r = 0; r < 4; ++r) {
            int i = i4 + r;
            float2 x0 = unpack2(oa[r][0]);
            float2 x1 = unpack2(oa[r][1]);
            *(float4*)&buf[i * VSTR + d0] = make_float4(x0.x, x0.y, x1.x, x1.y);
        }
    }
    __syncthreads();
    if (g == 0) {
#pragma unroll
        for (int r = 0; r < 4; ++r) {
            int i = i4 + r;
            float4 ov = *(const float4*)&buf[i * VSTR + d0];
            float2 x0 = unpack2(oa[r][0]);
            float2 x1 = unpack2(oa[r][1]);
            float4 res = make_float4(x0.x + ov.x, x0.y + ov.y, x1.x + ov.z, x1.y + ov.w);
            *(float4*)&g_AO[((size_t)bb * L + i0 + i) * HID + h * D + d0] = res;
        }
    }
}

// --------------------------------------------------------------------------
extern "C" void kernel_launch(void* const* d_in, const int* in_sizes, int n_in,
                              void* d_out, int out_size)
{
    const float* x   = (const float*)d_in[0];
    const float* qh  = (const float*)d_in[1];
    const float* qe  = (const float*)d_in[2];
    const float* kh  = (const float*)d_in[3];
    const float* ke  = (const float*)d_in[4];
    const float* vh  = (const float*)d_in[5];
    const float* ve  = (const float*)d_in[6];
    const int*   hop = (const int*)d_in[7];
    const int*   edg = (const int*)d_in[8];
    const float* Wq = (const float*)d_in[9];   const float* bq = (const float*)d_in[10];
    const float* Wk = (const float*)d_in[11];  const float* bk = (const float*)d_in[12];
    const float* Wv = (const float*)d_in[13];  const float* bv = (const float*)d_in[14];
    const float* Wo = (const float*)d_in[15];  const float* bo = (const float*)d_in[16];
    float* out = (float*)d_out;

    float *Qp, *Kp, *Vp, *AOp, *WTp;
    cudaGetSymbolAddress((void**)&Qp,  g_Q);
    cudaGetSymbolAddress((void**)&Kp,  g_K);
    cudaGetSymbolAddress((void**)&Vp,  g_V);
    cudaGetSymbolAddress((void**)&AOp, g_AO);
    cudaGetSymbolAddress((void**)&WTp, g_WT);

    const int projSmem = (64*64*2 + TT*EPAD*2) * (int)sizeof(float);
    const int attSmem  = ATT_SMEM_FLOATS * (int)sizeof(float);
    cudaFuncSetAttribute(proj_kernel, cudaFuncAttributeMaxDynamicSharedMemorySize, projSmem);
    cudaFuncSetAttribute(attn_kernel, cudaFuncAttributeMaxDynamicSharedMemorySize, attSmem);

    dim3 tg(HID / 32, HID / 32);
    dim3 tb(32, 8);
    dim3 gmm(ROWS / 128, HID / 128);
    dim3 gb(ROWS / GM, HID / GN);

    transpose_kernel<<<tg, tb>>>(Wq, WTp);
    gemm_mma_kernel<<<gmm, 256>>>(x, WTp, bq, Qp, 1);
    transpose_kernel<<<tg, tb>>>(Wk, WTp);
    gemm_mma_kernel<<<gmm, 256>>>(x, WTp, bk, Kp, 1);
    transpose_kernel<<<tg, tb>>>(Wv, WTp);
    gemm_mma_kernel<<<gmm, 256>>>(x, WTp, bv, Vp, 1);
    proj_kernel<<<dim3(BH, L / 64), 256, projSmem>>>(qh, qe, kh, ke);
    attn_kernel<<<dim3(L / AT_ROWS, BH), 256, attSmem>>>(hop, edg, vh, ve);
    gemm_kernel<<<gb, 256>>>(AOp, Wo, bo, out, 0);
}

// round 9
// speedup vs baseline: 1.8814x; 1.1875x over previous
#include <cuda_runtime.h>
#include <cstdint>

#define B 8
#define L 512
#define HID 768
#define NH 12
#define D 64
#define TH 32
#define TE 64
#define TT 96
#define BH (B*NH)
#define ROWS (B*L)

typedef unsigned long long ull;

__device__ __forceinline__ ull pack2(float lo, float hi) {
    ull r; asm("mov.b64 %0, {%1,%2};" : "=l"(r) : "f"(lo), "f"(hi)); return r;
}
__device__ __forceinline__ ull ffma2(ull a, ull b, ull c) {
    ull d; asm("fma.rn.f32x2 %0, %1, %2, %3;" : "=l"(d) : "l"(a), "l"(b), "l"(c)); return d;
}
__device__ __forceinline__ float2 unpack2(ull v) {
    float2 f; asm("mov.b64 {%0,%1}, %2;" : "=f"(f.x), "=f"(f.y) : "l"(v)); return f;
}
__device__ __forceinline__ uint32_t f2tf32(float x) {
    uint32_t u; asm("cvt.rna.tf32.f32 %0, %1;" : "=r"(u) : "f"(x)); return u;
}
__device__ __forceinline__ void mma_tf32(float* d, const uint32_t* a, const uint32_t* b) {
    asm volatile(
        "mma.sync.aligned.m16n8k8.row.col.f32.tf32.tf32.f32 "
        "{%0,%1,%2,%3}, {%4,%5,%6,%7}, {%8,%9}, {%0,%1,%2,%3};"
        : "+f"(d[0]), "+f"(d[1]), "+f"(d[2]), "+f"(d[3])
        : "r"(a[0]), "r"(a[1]), "r"(a[2]), "r"(a[3]), "r"(b[0]), "r"(b[1]));
}

// ---------------- scratch ----------------
__device__ float g_Q[BH*L*D];
__device__ float g_K[BH*L*D];
__device__ float g_V[BH*L*D];
__device__ float g_P[BH*L*TT];
__device__ float g_AO[ROWS*HID];
__device__ float g_WT[HID*HID];

// ---------------- W transpose: WT[n][k] = W[k][n] ----------------
__global__ __launch_bounds__(256) void transpose_kernel(
    const float* __restrict__ Wsrc, float* __restrict__ Wdst)
{
    __shared__ float t[32][33];
    int x  = blockIdx.x * 32 + threadIdx.x;
    int y0 = blockIdx.y * 32 + threadIdx.y;
#pragma unroll
    for (int dy = 0; dy < 32; dy += 8)
        t[threadIdx.y + dy][threadIdx.x] = Wsrc[(size_t)(y0 + dy) * HID + x];
    __syncthreads();
    int xo  = blockIdx.y * 32 + threadIdx.x;
    int yo0 = blockIdx.x * 32 + threadIdx.y;
#pragma unroll
    for (int dy = 0; dy < 32; dy += 8)
        Wdst[(size_t)(yo0 + dy) * HID + xo] = t[threadIdx.x][threadIdx.y + dy];
}

// ---------------- tf32 mma.sync GEMM: C = A[4096,768] @ W + bias -----------
#define KC 32
#define KCP 36          // row stride: (36g + t) mod 32 = 4g+t -> conflict-free frags

__global__ __launch_bounds__(256, 2) void gemm_mma_kernel(
    const float* __restrict__ A, const float* __restrict__ WT,
    const float* __restrict__ bias, float* __restrict__ Cout, int headLayout)
{
    __shared__ float As[128 * KCP];
    __shared__ float Bs[128 * KCP];

    const int tid = threadIdx.x;
    const int wid = tid >> 5, lane = tid & 31;
    const int g = lane >> 2, t = lane & 3;
    const int warp_m = wid & 3;
    const int warp_n = wid >> 2;
    const int row0 = blockIdx.x * 128, col0 = blockIdx.y * 128;

    float acc[2][8][4];
#pragma unroll
    for (int mf = 0; mf < 2; ++mf)
#pragma unroll
        for (int nf = 0; nf < 8; ++nf)
#pragma unroll
            for (int c = 0; c < 4; ++c) acc[mf][nf][c] = 0.f;

    const int mbase = warp_m * 32;
    const int nbase = warp_n * 64;

    for (int k0 = 0; k0 < HID; k0 += KC) {
#pragma unroll
        for (int it = 0; it < 4; ++it) {
            int idx = tid + it * 256;
            int r = idx >> 3, v = (idx & 7) << 2;
            float4 a = *(const float4*)&A[(size_t)(row0 + r) * HID + k0 + v];
            float4 b = *(const float4*)&WT[(size_t)(col0 + r) * HID + k0 + v];
            float* da = &As[r * KCP + v];
            da[0] = __uint_as_float(f2tf32(a.x)); da[1] = __uint_as_float(f2tf32(a.y));
            da[2] = __uint_as_float(f2tf32(a.z)); da[3] = __uint_as_float(f2tf32(a.w));
            float* db = &Bs[r * KCP + v];
            db[0] = __uint_as_float(f2tf32(b.x)); db[1] = __uint_as_float(f2tf32(b.y));
            db[2] = __uint_as_float(f2tf32(b.z)); db[3] = __uint_as_float(f2tf32(b.w));
        }
        __syncthreads();

#pragma unroll
        for (int kk = 0; kk < KC; kk += 8) {
            uint32_t bfr[8][2];
#pragma unroll
            for (int nf = 0; nf < 8; ++nf) {
                const float* bp = &Bs[(nbase + nf * 8 + g) * KCP + kk + t];
                bfr[nf][0] = __float_as_uint(bp[0]);
                bfr[nf][1] = __float_as_uint(bp[4]);
            }
            uint32_t afr[2][4];
#pragma unroll
            for (int mf = 0; mf < 2; ++mf) {
                const float* ap = &As[(mbase + mf * 16 + g) * KCP + kk + t];
                afr[mf][0] = __float_as_uint(ap[0]);
                afr[mf][1] = __float_as_uint(ap[8 * KCP]);
                afr[mf][2] = __float_as_uint(ap[4]);
                afr[mf][3] = __float_as_uint(ap[8 * KCP + 4]);
            }
#pragma unroll
            for (int mf = 0; mf < 2; ++mf)
#pragma unroll
                for (int nf = 0; nf < 8; ++nf)
                    mma_tf32(acc[mf][nf], afr[mf], bfr[nf]);
        }
        __syncthreads();
    }

#pragma unroll
    for (int mf = 0; mf < 2; ++mf) {
#pragma unroll
        for (int nf = 0; nf < 8; ++nf) {
            int row_a = row0 + mbase + mf * 16 + g;
            int col_a = col0 + nbase + nf * 8 + 2 * t;
#pragma unroll
            for (int half = 0; half < 2; ++half) {
                int row = row_a + half * 8;
                float2 v;
                v.x = acc[mf][nf][2 * half]     + bias[col_a];
                v.y = acc[mf][nf][2 * half + 1] + bias[col_a + 1];
                if (headLayout) {
                    int bb2 = row >> 9, ll = row & 511, hh = col_a >> 6, dd = col_a & 63;
                    *(float2*)&Cout[(((size_t)bb2 * NH + hh) * L + ll) * D + dd] = v;
                } else {
                    *(float2*)&Cout[(size_t)row * HID + col_a] = v;
                }
            }
        }
    }
}

// ---------------- proj via mma: P_bh[512,96] = [Q|K] @ [EQ_h|EK_h]^T -------
// A chunks: c=0,1 from g_Q (k 0..63), c=2,3 from g_K. B rows t<32 from hop
// tables, t>=32 from edge tables.
__global__ __launch_bounds__(256) void proj_mma_kernel(
    const float* __restrict__ qh, const float* __restrict__ qe,
    const float* __restrict__ kh, const float* __restrict__ ke)
{
    __shared__ float As[128 * KCP];
    __shared__ float Bs[TT * KCP];

    const int tid = threadIdx.x;
    const int wid = tid >> 5, lane = tid & 31;
    const int g = lane >> 2, t = lane & 3;
    const int warp_m = wid & 3;
    const int warp_n = wid >> 2;
    const int l0 = blockIdx.x * 128;
    const int bh = blockIdx.y;
    const int h  = bh % NH;

    float acc[2][6][4];
#pragma unroll
    for (int mf = 0; mf < 2; ++mf)
#pragma unroll
        for (int nf = 0; nf < 6; ++nf)
#pragma unroll
            for (int c = 0; c < 4; ++c) acc[mf][nf][c] = 0.f;

    const int mbase = warp_m * 32;
    const int nbase = warp_n * 48;

    for (int c = 0; c < 4; ++c) {
        const float* Asrc = (c < 2 ? g_Q : g_K) + ((size_t)bh * L + l0) * D + (c & 1) * 32;
        const float* E1 = (c < 2) ? qh : kh;     // hop table (t < 32)
        const float* E2 = (c < 2) ? qe : ke;     // edge table (t >= 32)
        const int koff = h * D + (c & 1) * 32;

        // stage A: 128 rows x 32 k (row stride D=64 in gmem)
#pragma unroll
        for (int it = 0; it < 4; ++it) {
            int idx = tid + it * 256;
            int r = idx >> 3, v = (idx & 7) << 2;
            float4 a = *(const float4*)&Asrc[(size_t)r * D + v];
            float* da = &As[r * KCP + v];
            da[0] = __uint_as_float(f2tf32(a.x)); da[1] = __uint_as_float(f2tf32(a.y));
            da[2] = __uint_as_float(f2tf32(a.z)); da[3] = __uint_as_float(f2tf32(a.w));
        }
        // stage B: 96 rows x 32 k
#pragma unroll
        for (int it = 0; it < 3; ++it) {
            int idx = tid + it * 256;
            int r = idx >> 3, v = (idx & 7) << 2;
            const float* src = (r < TH) ? &E1[(size_t)r * HID + koff + v]
                                        : &E2[(size_t)(r - TH) * HID + koff + v];
            float4 b = *(const float4*)src;
            float* db = &Bs[r * KCP + v];
            db[0] = __uint_as_float(f2tf32(b.x)); db[1] = __uint_as_float(f2tf32(b.y));
            db[2] = __uint_as_float(f2tf32(b.z)); db[3] = __uint_as_float(f2tf32(b.w));
        }
        __syncthreads();

#pragma unroll
        for (int kk = 0; kk < KC; kk += 8) {
            uint32_t bfr[6][2];
#pragma unroll
            for (int nf = 0; nf < 6; ++nf) {
                const float* bp = &Bs[(nbase + nf * 8 + g) * KCP + kk + t];
                bfr[nf][0] = __float_as_uint(bp[0]);
                bfr[nf][1] = __float_as_uint(bp[4]);
            }
            uint32_t afr[2][4];
#pragma unroll
            for (int mf = 0; mf < 2; ++mf) {
                const float* ap = &As[(mbase + mf * 16 + g) * KCP + kk + t];
                afr[mf][0] = __float_as_uint(ap[0]);
                afr[mf][1] = __float_as_uint(ap[8 * KCP]);
                afr[mf][2] = __float_as_uint(ap[4]);
                afr[mf][3] = __float_as_uint(ap[8 * KCP + 4]);
            }
#pragma unroll
            for (int mf = 0; mf < 2; ++mf)
#pragma unroll
                for (int nf = 0; nf < 6; ++nf)
                    mma_tf32(acc[mf][nf], afr[mf], bfr[nf]);
        }
        __syncthreads();
    }

    float* Pout = g_P + ((size_t)bh * L + l0) * TT;
#pragma unroll
    for (int mf = 0; mf < 2; ++mf) {
#pragma unroll
        for (int nf = 0; nf < 6; ++nf) {
            int row_a = mbase + mf * 16 + g;
            int col_a = nbase + nf * 8 + 2 * t;
#pragma unroll
            for (int half = 0; half < 2; ++half) {
                int row = row_a + half * 8;
                float2 v;
                v.x = acc[mf][nf][2 * half];
                v.y = acc[mf][nf][2 * half + 1];
                *(float2*)&Pout[(size_t)row * TT + col_a] = v;
            }
        }
    }
}

// ---------------- attention (unchanged from R6 win) ----------------
#define AT_ROWS 32
#define SCS 516
#define KSTR 132
#define VSTR 68
#define BUF_FLOATS (128*VSTR)
#define ATT_SMEM_FLOATS (AT_ROWS*SCS + AT_ROWS*64 + AT_ROWS*TT + AT_ROWS*TT + BUF_FLOATS)

__global__ __launch_bounds__(256) void attn_kernel(
    const int* __restrict__ hop, const int* __restrict__ edge,
    const float* __restrict__ vh, const float* __restrict__ ve)
{
    extern __shared__ float sm[];
    float* sc   = sm;
    float* qs   = sc + AT_ROWS * SCS;
    float* Ps   = qs + AT_ROWS * 64;
    float* bins = Ps + AT_ROWS * TT;
    float* buf  = bins + AT_ROWS * TT;

    const int bh = blockIdx.y;
    const int bb = bh / NH, h = bh % NH;
    const int i0 = blockIdx.x * AT_ROWS;
    const int tid = threadIdx.x;
    const float scale = 0.125f;

    {
        const float* Qp = g_Q + ((size_t)bh * L + i0) * D;
        for (int idx = tid; idx < AT_ROWS * D; idx += 256) qs[idx] = Qp[idx];
        const float* Pp = g_P + ((size_t)bh * L + i0) * TT;
        for (int idx = tid; idx < AT_ROWS * TT; idx += 256) { Ps[idx] = Pp[idx]; bins[idx] = 0.f; }
    }

    const size_t hopBase = ((size_t)bb * L + i0) * L;

    const int jg = tid & 31;
    const int ig = tid >> 5;
    const int j0 = jg * 4;
    const int ib4 = ig * 4;

    for (int jc = 0; jc < L; jc += 128) {
        const float* Kp = g_K + ((size_t)bh * L + jc) * D;
        for (int idx4 = tid; idx4 < 2048; idx4 += 256) {
            int jj = idx4 >> 4, dd4 = (idx4 & 15) << 2;
            float4 kv = *(const float4*)&Kp[(size_t)jj * D + dd4];
            buf[(dd4 + 0) * KSTR + jj] = kv.x;
            buf[(dd4 + 1) * KSTR + jj] = kv.y;
            buf[(dd4 + 2) * KSTR + jj] = kv.z;
            buf[(dd4 + 3) * KSTR + jj] = kv.w;
        }
        __syncthreads();

        ull acc[4][2];
#pragma unroll
        for (int r = 0; r < 4; ++r) { acc[r][0] = 0ull; acc[r][1] = 0ull; }

        for (int dd = 0; dd < D; ++dd) {
            float4 kj = *(const float4*)&buf[dd * KSTR + j0];
            ull k01 = ((const ull*)&kj)[0];
            ull k23 = ((const ull*)&kj)[1];
#pragma unroll
            for (int r = 0; r < 4; ++r) {
                float qv = qs[(ib4 + r) * D + dd];
                ull qq = pack2(qv, qv);
                acc[r][0] = ffma2(qq, k01, acc[r][0]);
                acc[r][1] = ffma2(qq, k23, acc[r][1]);
            }
        }

#pragma unroll
        for (int r = 0; r < 4; ++r) {
            int i = ib4 + r;
            const int4 hp = *(const int4*)&hop [hopBase + (size_t)i * L + jc + j0];
            const int4 ep = *(const int4*)&edge[hopBase + (size_t)i * L + jc + j0];
            float2 a0 = unpack2(acc[r][0]);
            float2 a1 = unpack2(acc[r][1]);
            const float* prow = Ps + i * TT;
            float* srow = sc + i * SCS + jc + j0;
            srow[0] = a0.x + prow[hp.x] + prow[TH + ep.x];
            srow[1] = a0.y + prow[hp.y] + prow[TH + ep.y];
            srow[2] = a1.x + prow[hp.z] + prow[TH + ep.z];
            srow[3] = a1.y + prow[hp.w] + prow[TH + ep.w];
        }
        __syncthreads();
    }

    {
        const int warp = tid >> 5, lane = tid & 31;
        for (int i = warp * 4; i < warp * 4 + 4; ++i) {
            float* srow = sc + i * SCS;
            float m = -1e30f;
            for (int j = lane; j < L; j += 32) m = fmaxf(m, srow[j]);
#pragma unroll
            for (int off = 16; off > 0; off >>= 1) m = fmaxf(m, __shfl_xor_sync(0xffffffffu, m, off));
            float sum = 0.f;
            for (int j = lane; j < L; j += 32) {
                float e = __expf((srow[j] - m) * scale);
                srow[j] = e;
                sum += e;
            }
#pragma unroll
            for (int off = 16; off > 0; off >>= 1) sum += __shfl_xor_sync(0xffffffffu, sum, off);
            float rinv = 1.f / sum;
            const int* hr = hop  + hopBase + (size_t)i * L;
            const int* er = edge + hopBase + (size_t)i * L;
            for (int j = lane; j < L; j += 32) {
                float a = srow[j] * rinv;
                srow[j] = a;
                atomicAdd(&bins[i * TT + hr[j]], a);
                atomicAdd(&bins[i * TT + TH + er[j]], a);
            }
        }
    }
    __syncthreads();

    const int g   = tid >> 7;
    const int t2  = tid & 127;
    const int ig2 = t2 >> 4;
    const int dg  = t2 & 15;
    const int i4  = ig2 * 4;
    const int d0  = dg * 4;

    ull oa[4][2];
#pragma unroll
    for (int r = 0; r < 4; ++r) { oa[r][0] = 0ull; oa[r][1] = 0ull; }

    for (int jc = 0; jc < L; jc += 128) {
        const float* Vp = g_V + ((size_t)bh * L + jc) * D;
        for (int idx4 = tid; idx4 < 2048; idx4 += 256) {
            int jj = idx4 >> 4, dd4 = (idx4 & 15) << 2;
            *(float4*)&buf[jj * VSTR + dd4] = *(const float4*)&Vp[(size_t)jj * D + dd4];
        }
        __syncthreads();

        for (int jj = g; jj < 128; jj += 2) {
            float4 vv = *(const float4*)&buf[jj * VSTR + d0];
            ull v01 = ((const ull*)&vv)[0];
            ull v23 = ((const ull*)&vv)[1];
#pragma unroll
            for (int r = 0; r < 4; ++r) {
                float av = sc[(i4 + r) * SCS + jc + jj];
                ull aa = pack2(av, av);
                oa[r][0] = ffma2(aa, v01, oa[r][0]);
                oa[r][1] = ffma2(aa, v23, oa[r][1]);
            }
        }
        __syncthreads();
    }

    for (int idx = tid; idx < TT * D; idx += 256) {
        int t = idx >> 6, d2 = idx & 63;
        buf[t * VSTR + d2] = (t < TH) ? vh[(size_t)t * HID + h * D + d2]
                                      : ve[(size_t)(t - TH) * HID + h * D + d2];
    }
    __syncthreads();

    for (int t = 48 * g; t < 48 * g + 48; ++t) {
        float4 vv = *(const float4*)&buf[t * VSTR + d0];
        ull v01 = ((const ull*)&vv)[0];
        ull v23 = ((const ull*)&vv)[1];
#pragma unroll
        for (int r = 0; r < 4; ++r) {
            float bv = bins[(i4 + r) * TT + t];
            ull aa = pack2(bv, bv);
            oa[r][0] = ffma2(aa, v01, oa[r][0]);
            oa[r][1] = ffma2(aa, v23, oa[r][1]);
        }
    }
    __syncthreads();

    if (g == 1) {
#pragma unroll
        for (int r = 0; r < 4; ++r) {
            int i = i4 + r;
            float2 x0 = unpack2(oa[r][0]);
            float2 x1 = unpack2(oa[r][1]);
            *(float4*)&buf[i * VSTR + d0] = make_float4(x0.x, x0.y, x1.x, x1.y);
        }
    }
    __syncthreads();
    if (g == 0) {
#pragma unroll
        for (int r = 0; r < 4; ++r) {
            int i = i4 + r;
            float4 ov = *(const float4*)&buf[i * VSTR + d0];
            float2 x0 = unpack2(oa[r][0]);
            float2 x1 = unpack2(oa[r][1]);
            float4 res = make_float4(x0.x + ov.x, x0.y + ov.y, x1.x + ov.z, x1.y + ov.w);
            *(float4*)&g_AO[((size_t)bb * L + i0 + i) * HID + h * D + d0] = res;
        }
    }
}

// --------------------------------------------------------------------------
extern "C" void kernel_launch(void* const* d_in, const int* in_sizes, int n_in,
                              void* d_out, int out_size)
{
    const float* x   = (const float*)d_in[0];
    const float* qh  = (const float*)d_in[1];
    const float* qe  = (const float*)d_in[2];
    const float* kh  = (const float*)d_in[3];
    const float* ke  = (const float*)d_in[4];
    const float* vh  = (const float*)d_in[5];
    const float* ve  = (const float*)d_in[6];
    const int*   hop = (const int*)d_in[7];
    const int*   edg = (const int*)d_in[8];
    const float* Wq = (const float*)d_in[9];   const float* bq = (const float*)d_in[10];
    const float* Wk = (const float*)d_in[11];  const float* bk = (const float*)d_in[12];
    const float* Wv = (const float*)d_in[13];  const float* bv = (const float*)d_in[14];
    const float* Wo = (const float*)d_in[15];  const float* bo = (const float*)d_in[16];
    float* out = (float*)d_out;

    float *Qp, *Kp, *Vp, *AOp, *WTp;
    cudaGetSymbolAddress((void**)&Qp,  g_Q);
    cudaGetSymbolAddress((void**)&Kp,  g_K);
    cudaGetSymbolAddress((void**)&Vp,  g_V);
    cudaGetSymbolAddress((void**)&AOp, g_AO);
    cudaGetSymbolAddress((void**)&WTp, g_WT);

    const int attSmem = ATT_SMEM_FLOATS * (int)sizeof(float);
    cudaFuncSetAttribute(attn_kernel, cudaFuncAttributeMaxDynamicSharedMemorySize, attSmem);

    dim3 tg(HID / 32, HID / 32);
    dim3 tb(32, 8);
    dim3 gmm(ROWS / 128, HID / 128);

    transpose_kernel<<<tg, tb>>>(Wq, WTp);
    gemm_mma_kernel<<<gmm, 256>>>(x, WTp, bq, Qp, 1);
    transpose_kernel<<<tg, tb>>>(Wk, WTp);
    gemm_mma_kernel<<<gmm, 256>>>(x, WTp, bk, Kp, 1);
    transpose_kernel<<<tg, tb>>>(Wv, WTp);
    gemm_mma_kernel<<<gmm, 256>>>(x, WTp, bv, Vp, 1);
    proj_mma_kernel<<<dim3(L / 128, BH), 256>>>(qh, qe, kh, ke);
    attn_kernel<<<dim3(L / AT_ROWS, BH), 256, attSmem>>>(hop, edg, vh, ve);
    transpose_kernel<<<tg, tb>>>(Wo, WTp);
    gemm_mma_kernel<<<gmm, 256>>>(AOp, WTp, bo, out, 0);
}

// round 10
// speedup vs baseline: 3.0156x; 1.6029x over previous
#include <cuda_runtime.h>
#include <cstdint>

#define B 8
#define L 512
#define HID 768
#define NH 12
#define D 64
#define TH 32
#define TE 64
#define TT 96
#define BH (B*NH)
#define ROWS (B*L)

typedef unsigned long long ull;

__device__ __forceinline__ ull pack2(float lo, float hi) {
    ull r; asm("mov.b64 %0, {%1,%2};" : "=l"(r) : "f"(lo), "f"(hi)); return r;
}
__device__ __forceinline__ ull ffma2(ull a, ull b, ull c) {
    ull d; asm("fma.rn.f32x2 %0, %1, %2, %3;" : "=l"(d) : "l"(a), "l"(b), "l"(c)); return d;
}
__device__ __forceinline__ float2 unpack2(ull v) {
    float2 f; asm("mov.b64 {%0,%1}, %2;" : "=f"(f.x), "=f"(f.y) : "l"(v)); return f;
}
__device__ __forceinline__ uint32_t f2tf32(float x) {
    uint32_t u; asm("cvt.rna.tf32.f32 %0, %1;" : "=r"(u) : "f"(x)); return u;
}
__device__ __forceinline__ void mma_tf32(float* d, const uint32_t* a, const uint32_t* b) {
    asm volatile(
        "mma.sync.aligned.m16n8k8.row.col.f32.tf32.tf32.f32 "
        "{%0,%1,%2,%3}, {%4,%5,%6,%7}, {%8,%9}, {%0,%1,%2,%3};"
        : "+f"(d[0]), "+f"(d[1]), "+f"(d[2]), "+f"(d[3])
        : "r"(a[0]), "r"(a[1]), "r"(a[2]), "r"(a[3]), "r"(b[0]), "r"(b[1]));
}

// ---------------- scratch ----------------
__device__ float g_Q[BH*L*D];
__device__ float g_K[BH*L*D];
__device__ float g_V[BH*L*D];
__device__ float g_P[BH*L*TT];
__device__ float g_AO[ROWS*HID];
__device__ float g_WT[HID*HID];

// ---------------- W transpose ----------------
__global__ __launch_bounds__(256) void transpose_kernel(
    const float* __restrict__ Wsrc, float* __restrict__ Wdst)
{
    __shared__ float t[32][33];
    int x  = blockIdx.x * 32 + threadIdx.x;
    int y0 = blockIdx.y * 32 + threadIdx.y;
#pragma unroll
    for (int dy = 0; dy < 32; dy += 8)
        t[threadIdx.y + dy][threadIdx.x] = Wsrc[(size_t)(y0 + dy) * HID + x];
    __syncthreads();
    int xo  = blockIdx.y * 32 + threadIdx.x;
    int yo0 = blockIdx.x * 32 + threadIdx.y;
#pragma unroll
    for (int dy = 0; dy < 32; dy += 8)
        Wdst[(size_t)(yo0 + dy) * HID + xo] = t[threadIdx.x][threadIdx.y + dy];
}

// ---------------- tf32 mma.sync GEMM ----------------
#define KC 32
#define KCP 36

__global__ __launch_bounds__(256, 2) void gemm_mma_kernel(
    const float* __restrict__ A, const float* __restrict__ WT,
    const float* __restrict__ bias, float* __restrict__ Cout, int headLayout)
{
    __shared__ float As[128 * KCP];
    __shared__ float Bs[128 * KCP];

    const int tid = threadIdx.x;
    const int wid = tid >> 5, lane = tid & 31;
    const int g = lane >> 2, t = lane & 3;
    const int warp_m = wid & 3;
    const int warp_n = wid >> 2;
    const int row0 = blockIdx.x * 128, col0 = blockIdx.y * 128;

    float acc[2][8][4];
#pragma unroll
    for (int mf = 0; mf < 2; ++mf)
#pragma unroll
        for (int nf = 0; nf < 8; ++nf)
#pragma unroll
            for (int c = 0; c < 4; ++c) acc[mf][nf][c] = 0.f;

    const int mbase = warp_m * 32;
    const int nbase = warp_n * 64;

    for (int k0 = 0; k0 < HID; k0 += KC) {
#pragma unroll
        for (int it = 0; it < 4; ++it) {
            int idx = tid + it * 256;
            int r = idx >> 3, v = (idx & 7) << 2;
            float4 a = *(const float4*)&A[(size_t)(row0 + r) * HID + k0 + v];
            float4 b = *(const float4*)&WT[(size_t)(col0 + r) * HID + k0 + v];
            float* da = &As[r * KCP + v];
            da[0] = __uint_as_float(f2tf32(a.x)); da[1] = __uint_as_float(f2tf32(a.y));
            da[2] = __uint_as_float(f2tf32(a.z)); da[3] = __uint_as_float(f2tf32(a.w));
            float* db = &Bs[r * KCP + v];
            db[0] = __uint_as_float(f2tf32(b.x)); db[1] = __uint_as_float(f2tf32(b.y));
            db[2] = __uint_as_float(f2tf32(b.z)); db[3] = __uint_as_float(f2tf32(b.w));
        }
        __syncthreads();

#pragma unroll
        for (int kk = 0; kk < KC; kk += 8) {
            uint32_t bfr[8][2];
#pragma unroll
            for (int nf = 0; nf < 8; ++nf) {
                const float* bp = &Bs[(nbase + nf * 8 + g) * KCP + kk + t];
                bfr[nf][0] = __float_as_uint(bp[0]);
                bfr[nf][1] = __float_as_uint(bp[4]);
            }
            uint32_t afr[2][4];
#pragma unroll
            for (int mf = 0; mf < 2; ++mf) {
                const float* ap = &As[(mbase + mf * 16 + g) * KCP + kk + t];
                afr[mf][0] = __float_as_uint(ap[0]);
                afr[mf][1] = __float_as_uint(ap[8 * KCP]);
                afr[mf][2] = __float_as_uint(ap[4]);
                afr[mf][3] = __float_as_uint(ap[8 * KCP + 4]);
            }
#pragma unroll
            for (int mf = 0; mf < 2; ++mf)
#pragma unroll
                for (int nf = 0; nf < 8; ++nf)
                    mma_tf32(acc[mf][nf], afr[mf], bfr[nf]);
        }
        __syncthreads();
    }

#pragma unroll
    for (int mf = 0; mf < 2; ++mf) {
#pragma unroll
        for (int nf = 0; nf < 8; ++nf) {
            int row_a = row0 + mbase + mf * 16 + g;
            int col_a = col0 + nbase + nf * 8 + 2 * t;
#pragma unroll
            for (int half = 0; half < 2; ++half) {
                int row = row_a + half * 8;
                float2 v;
                v.x = acc[mf][nf][2 * half]     + bias[col_a];
                v.y = acc[mf][nf][2 * half + 1] + bias[col_a + 1];
                if (headLayout) {
                    int bb2 = row >> 9, ll = row & 511, hh = col_a >> 6, dd = col_a & 63;
                    *(float2*)&Cout[(((size_t)bb2 * NH + hh) * L + ll) * D + dd] = v;
                } else {
                    *(float2*)&Cout[(size_t)row * HID + col_a] = v;
                }
            }
        }
    }
}

// ---------------- proj via mma (unchanged from R9 win) ----------------
__global__ __launch_bounds__(256) void proj_mma_kernel(
    const float* __restrict__ qh, const float* __restrict__ qe,
    const float* __restrict__ kh, const float* __restrict__ ke)
{
    __shared__ float As[128 * KCP];
    __shared__ float Bs[TT * KCP];

    const int tid = threadIdx.x;
    const int wid = tid >> 5, lane = tid & 31;
    const int g = lane >> 2, t = lane & 3;
    const int warp_m = wid & 3;
    const int warp_n = wid >> 2;
    const int l0 = blockIdx.x * 128;
    const int bh = blockIdx.y;
    const int h  = bh % NH;

    float acc[2][6][4];
#pragma unroll
    for (int mf = 0; mf < 2; ++mf)
#pragma unroll
        for (int nf = 0; nf < 6; ++nf)
#pragma unroll
            for (int c = 0; c < 4; ++c) acc[mf][nf][c] = 0.f;

    const int mbase = warp_m * 32;
    const int nbase = warp_n * 48;

    for (int c = 0; c < 4; ++c) {
        const float* Asrc = (c < 2 ? g_Q : g_K) + ((size_t)bh * L + l0) * D + (c & 1) * 32;
        const float* E1 = (c < 2) ? qh : kh;
        const float* E2 = (c < 2) ? qe : ke;
        const int koff = h * D + (c & 1) * 32;

#pragma unroll
        for (int it = 0; it < 4; ++it) {
            int idx = tid + it * 256;
            int r = idx >> 3, v = (idx & 7) << 2;
            float4 a = *(const float4*)&Asrc[(size_t)r * D + v];
            float* da = &As[r * KCP + v];
            da[0] = __uint_as_float(f2tf32(a.x)); da[1] = __uint_as_float(f2tf32(a.y));
            da[2] = __uint_as_float(f2tf32(a.z)); da[3] = __uint_as_float(f2tf32(a.w));
        }
#pragma unroll
        for (int it = 0; it < 3; ++it) {
            int idx = tid + it * 256;
            int r = idx >> 3, v = (idx & 7) << 2;
            const float* src = (r < TH) ? &E1[(size_t)r * HID + koff + v]
                                        : &E2[(size_t)(r - TH) * HID + koff + v];
            float4 b = *(const float4*)src;
            float* db = &Bs[r * KCP + v];
            db[0] = __uint_as_float(f2tf32(b.x)); db[1] = __uint_as_float(f2tf32(b.y));
            db[2] = __uint_as_float(f2tf32(b.z)); db[3] = __uint_as_float(f2tf32(b.w));
        }
        __syncthreads();

#pragma unroll
        for (int kk = 0; kk < KC; kk += 8) {
            uint32_t bfr[6][2];
#pragma unroll
            for (int nf = 0; nf < 6; ++nf) {
                const float* bp = &Bs[(nbase + nf * 8 + g) * KCP + kk + t];
                bfr[nf][0] = __float_as_uint(bp[0]);
                bfr[nf][1] = __float_as_uint(bp[4]);
            }
            uint32_t afr[2][4];
#pragma unroll
            for (int mf = 0; mf < 2; ++mf) {
                const float* ap = &As[(mbase + mf * 16 + g) * KCP + kk + t];
                afr[mf][0] = __float_as_uint(ap[0]);
                afr[mf][1] = __float_as_uint(ap[8 * KCP]);
                afr[mf][2] = __float_as_uint(ap[4]);
                afr[mf][3] = __float_as_uint(ap[8 * KCP + 4]);
            }
#pragma unroll
            for (int mf = 0; mf < 2; ++mf)
#pragma unroll
                for (int nf = 0; nf < 6; ++nf)
                    mma_tf32(acc[mf][nf], afr[mf], bfr[nf]);
        }
        __syncthreads();
    }

    float* Pout = g_P + ((size_t)bh * L + l0) * TT;
#pragma unroll
    for (int mf = 0; mf < 2; ++mf) {
#pragma unroll
        for (int nf = 0; nf < 6; ++nf) {
            int row_a = mbase + mf * 16 + g;
            int col_a = nbase + nf * 8 + 2 * t;
#pragma unroll
            for (int half = 0; half < 2; ++half) {
                int row = row_a + half * 8;
                float2 v;
                v.x = acc[mf][nf][2 * half];
                v.y = acc[mf][nf][2 * half + 1];
                *(float2*)&Pout[(size_t)row * TT + col_a] = v;
            }
        }
    }
}

// ---------------- attention: single-pass, no-max softmax, raw-e bins -------
#define AT_ROWS 32
#define ESS 132                 // e-chunk row stride
#define KSTR 132                // K^T stage stride
#define VSTR 68                 // V / VE stage stride
#define BUF_FLOATS (128*VSTR)   // 8704 >= 64*KSTR(8448)
// qs + Ps + bins + es + buf + rs
#define ATT_SMEM_FLOATS (AT_ROWS*64 + AT_ROWS*TT + AT_ROWS*TT + AT_ROWS*ESS + BUF_FLOATS + 32)

__global__ __launch_bounds__(256) void attn_kernel(
    const int* __restrict__ hop, const int* __restrict__ edge,
    const float* __restrict__ vh, const float* __restrict__ ve)
{
    extern __shared__ float sm[];
    float* qs   = sm;                      // [32][64]
    float* Ps   = qs + AT_ROWS * 64;       // [32][96]
    float* bins = Ps + AT_ROWS * TT;       // [32][96]
    float* es   = bins + AT_ROWS * TT;     // [32][132] chunk of raw e
    float* buf  = es + AT_ROWS * ESS;      // K^T / V / VE staging
    float* rs   = buf + BUF_FLOATS;        // [32] 1/rowsum

    const int bh = blockIdx.y;
    const int bb = bh / NH, h = bh % NH;
    const int i0 = blockIdx.x * AT_ROWS;
    const int tid = threadIdx.x;
    const float scale = 0.125f;

    {
        const float* Qp = g_Q + ((size_t)bh * L + i0) * D;
        for (int idx = tid; idx < AT_ROWS * D; idx += 256) qs[idx] = Qp[idx];
        const float* Pp = g_P + ((size_t)bh * L + i0) * TT;
        for (int idx = tid; idx < AT_ROWS * TT; idx += 256) { Ps[idx] = Pp[idx]; bins[idx] = 0.f; }
    }

    const size_t hopBase = ((size_t)bb * L + i0) * L;

    // score layout: warp = 4 rows, lanes cover chunk j (4 each)
    const int jg = tid & 31;
    const int ig = tid >> 5;
    const int j0 = jg * 4;
    const int ib4 = ig * 4;

    // AV layout
    const int gv  = tid >> 7;
    const int t2  = tid & 127;
    const int ig2 = t2 >> 4;
    const int dg  = t2 & 15;
    const int i4  = ig2 * 4;
    const int d0  = dg * 4;

    float lsum[4] = {0.f, 0.f, 0.f, 0.f};
    ull oa[4][2];
#pragma unroll
    for (int r = 0; r < 4; ++r) { oa[r][0] = 0ull; oa[r][1] = 0ull; }

    for (int jc = 0; jc < L; jc += 128) {
        // ---- stage K^T chunk: buf[dd][j'] ----
        const float* Kp = g_K + ((size_t)bh * L + jc) * D;
        for (int idx4 = tid; idx4 < 2048; idx4 += 256) {
            int jj = idx4 >> 4, dd4 = (idx4 & 15) << 2;
            float4 kv = *(const float4*)&Kp[(size_t)jj * D + dd4];
            buf[(dd4 + 0) * KSTR + jj] = kv.x;
            buf[(dd4 + 1) * KSTR + jj] = kv.y;
            buf[(dd4 + 2) * KSTR + jj] = kv.z;
            buf[(dd4 + 3) * KSTR + jj] = kv.w;
        }
        __syncthreads();

        // ---- scores tile ----
        ull acc[4][2];
#pragma unroll
        for (int r = 0; r < 4; ++r) { acc[r][0] = 0ull; acc[r][1] = 0ull; }

        for (int dd = 0; dd < D; ++dd) {
            float4 kj = *(const float4*)&buf[dd * KSTR + j0];
            ull k01 = ((const ull*)&kj)[0];
            ull k23 = ((const ull*)&kj)[1];
#pragma unroll
            for (int r = 0; r < 4; ++r) {
                float qv = qs[(ib4 + r) * D + dd];
                ull qq = pack2(qv, qv);
                acc[r][0] = ffma2(qq, k01, acc[r][0]);
                acc[r][1] = ffma2(qq, k23, acc[r][1]);
            }
        }

        // ---- e = exp(scale*(s + bias)), scatter raw e into bins, rowsum ----
#pragma unroll
        for (int r = 0; r < 4; ++r) {
            int i = ib4 + r;
            const int4 hp = *(const int4*)&hop [hopBase + (size_t)i * L + jc + j0];
            const int4 ep = *(const int4*)&edge[hopBase + (size_t)i * L + jc + j0];
            float2 a0 = unpack2(acc[r][0]);
            float2 a1 = unpack2(acc[r][1]);
            const float* prow = Ps + i * TT;
            float s0 = (a0.x + prow[hp.x] + prow[TH + ep.x]) * scale;
            float s1 = (a0.y + prow[hp.y] + prow[TH + ep.y]) * scale;
            float s2 = (a1.x + prow[hp.z] + prow[TH + ep.z]) * scale;
            float s3 = (a1.y + prow[hp.w] + prow[TH + ep.w]) * scale;
            float e0 = __expf(fminf(fmaxf(s0, -70.f), 70.f));
            float e1 = __expf(fminf(fmaxf(s1, -70.f), 70.f));
            float e2 = __expf(fminf(fmaxf(s2, -70.f), 70.f));
            float e3 = __expf(fminf(fmaxf(s3, -70.f), 70.f));
            float* erow = es + i * ESS + j0;
            erow[0] = e0; erow[1] = e1; erow[2] = e2; erow[3] = e3;
            lsum[r] += (e0 + e1) + (e2 + e3);
            float* brow = bins + i * TT;
            atomicAdd(&brow[hp.x], e0);      atomicAdd(&brow[TH + ep.x], e0);
            atomicAdd(&brow[hp.y], e1);      atomicAdd(&brow[TH + ep.y], e1);
            atomicAdd(&brow[hp.z], e2);      atomicAdd(&brow[TH + ep.z], e2);
            atomicAdd(&brow[hp.w], e3);      atomicAdd(&brow[TH + ep.w], e3);
        }
        __syncthreads();       // es complete; buf (K) free

        // ---- stage V chunk: buf[j'][dd] ----
        const float* Vp = g_V + ((size_t)bh * L + jc) * D;
        for (int idx4 = tid; idx4 < 2048; idx4 += 256) {
            int jj = idx4 >> 4, dd4 = (idx4 & 15) << 2;
            *(float4*)&buf[jj * VSTR + dd4] = *(const float4*)&Vp[(size_t)jj * D + dd4];
        }
        __syncthreads();

        // ---- AV accumulate ----
        for (int jj = gv; jj < 128; jj += 2) {
            float4 vv = *(const float4*)&buf[jj * VSTR + d0];
            ull v01 = ((const ull*)&vv)[0];
            ull v23 = ((const ull*)&vv)[1];
#pragma unroll
            for (int r = 0; r < 4; ++r) {
                float av = es[(i4 + r) * ESS + jj];
                ull aa = pack2(av, av);
                oa[r][0] = ffma2(aa, v01, oa[r][0]);
                oa[r][1] = ffma2(aa, v23, oa[r][1]);
            }
        }
        __syncthreads();       // es + buf free for next chunk
    }

    // ---- row sums -> rs (warp-local reduce; rows ib4..ib4+3 owned by warp ig)
#pragma unroll
    for (int r = 0; r < 4; ++r) {
        float v = lsum[r];
#pragma unroll
        for (int off = 16; off > 0; off >>= 1) v += __shfl_xor_sync(0xffffffffu, v, off);
        if (jg == 0) rs[ib4 + r] = 1.f / v;
    }

    // ---- stage type-value embeddings ----
    for (int idx = tid; idx < TT * D; idx += 256) {
        int t = idx >> 6, d2 = idx & 63;
        buf[t * VSTR + d2] = (t < TH) ? vh[(size_t)t * HID + h * D + d2]
                                      : ve[(size_t)(t - TH) * HID + h * D + d2];
    }
    __syncthreads();

    // ---- bins x VE ----
    for (int t = 48 * gv; t < 48 * gv + 48; ++t) {
        float4 vv = *(const float4*)&buf[t * VSTR + d0];
        ull v01 = ((const ull*)&vv)[0];
        ull v23 = ((const ull*)&vv)[1];
#pragma unroll
        for (int r = 0; r < 4; ++r) {
            float bv = bins[(i4 + r) * TT + t];
            ull aa = pack2(bv, bv);
            oa[r][0] = ffma2(aa, v01, oa[r][0]);
            oa[r][1] = ffma2(aa, v23, oa[r][1]);
        }
    }
    __syncthreads();

    // ---- reduce j-parity halves, normalize, write ----
    if (gv == 1) {
#pragma unroll
        for (int r = 0; r < 4; ++r) {
            int i = i4 + r;
            float2 x0 = unpack2(oa[r][0]);
            float2 x1 = unpack2(oa[r][1]);
            *(float4*)&buf[i * VSTR + d0] = make_float4(x0.x, x0.y, x1.x, x1.y);
        }
    }
    __syncthreads();
    if (gv == 0) {
#pragma unroll
        for (int r = 0; r < 4; ++r) {
            int i = i4 + r;
            float rinv = rs[i];
            float4 ov = *(const float4*)&buf[i * VSTR + d0];
            float2 x0 = unpack2(oa[r][0]);
            float2 x1 = unpack2(oa[r][1]);
            float4 res = make_float4((x0.x + ov.x) * rinv, (x0.y + ov.y) * rinv,
                                     (x1.x + ov.z) * rinv, (x1.y + ov.w) * rinv);
            *(float4*)&g_AO[((size_t)bb * L + i0 + i) * HID + h * D + d0] = res;
        }
    }
}

// --------------------------------------------------------------------------
extern "C" void kernel_launch(void* const* d_in, const int* in_sizes, int n_in,
                              void* d_out, int out_size)
{
    const float* x   = (const float*)d_in[0];
    const float* qh  = (const float*)d_in[1];
    const float* qe  = (const float*)d_in[2];
    const float* kh  = (const float*)d_in[3];
    const float* ke  = (const float*)d_in[4];
    const float* vh  = (const float*)d_in[5];
    const float* ve  = (const float*)d_in[6];
    const int*   hop = (const int*)d_in[7];
    const int*   edg = (const int*)d_in[8];
    const float* Wq = (const float*)d_in[9];   const float* bq = (const float*)d_in[10];
    const float* Wk = (const float*)d_in[11];  const float* bk = (const float*)d_in[12];
    const float* Wv = (const float*)d_in[13];  const float* bv = (const float*)d_in[14];
    const float* Wo = (const float*)d_in[15];  const float* bo = (const float*)d_in[16];
    float* out = (float*)d_out;

    float *Qp, *Kp, *Vp, *AOp, *WTp;
    cudaGetSymbolAddress((void**)&Qp,  g_Q);
    cudaGetSymbolAddress((void**)&Kp,  g_K);
    cudaGetSymbolAddress((void**)&Vp,  g_V);
    cudaGetSymbolAddress((void**)&AOp, g_AO);
    cudaGetSymbolAddress((void**)&WTp, g_WT);

    const int attSmem = ATT_SMEM_FLOATS * (int)sizeof(float);
    cudaFuncSetAttribute(attn_kernel, cudaFuncAttributeMaxDynamicSharedMemorySize, attSmem);

    dim3 tg(HID / 32, HID / 32);
    dim3 tb(32, 8);
    dim3 gmm(ROWS / 128, HID / 128);

    transpose_kernel<<<tg, tb>>>(Wq, WTp);
    gemm_mma_kernel<<<gmm, 256>>>(x, WTp, bq, Qp, 1);
    transpose_kernel<<<tg, tb>>>(Wk, WTp);
    gemm_mma_kernel<<<gmm, 256>>>(x, WTp, bk, Kp, 1);
    transpose_kernel<<<tg, tb>>>(Wv, WTp);
    gemm_mma_kernel<<<gmm, 256>>>(x, WTp, bv, Vp, 1);
    proj_mma_kernel<<<dim3(L / 128, BH), 256>>>(qh, qe, kh, ke);
    attn_kernel<<<dim3(L / AT_ROWS, BH), 256, attSmem>>>(hop, edg, vh, ve);
    transpose_kernel<<<tg, tb>>>(Wo, WTp);
    gemm_mma_kernel<<<gmm, 256>>>(AOp, WTp, bo, out, 0);
}

// round 11
// speedup vs baseline: 3.3673x; 1.1166x over previous
#include <cuda_runtime.h>
#include <cstdint>

#define B 8
#define L 512
#define HID 768
#define NH 12
#define D 64
#define TH 32
#define TE 64
#define TT 96
#define BH (B*NH)
#define ROWS (B*L)

typedef unsigned long long ull;

__device__ __forceinline__ ull pack2(float lo, float hi) {
    ull r; asm("mov.b64 %0, {%1,%2};" : "=l"(r) : "f"(lo), "f"(hi)); return r;
}
__device__ __forceinline__ ull ffma2(ull a, ull b, ull c) {
    ull d; asm("fma.rn.f32x2 %0, %1, %2, %3;" : "=l"(d) : "l"(a), "l"(b), "l"(c)); return d;
}
__device__ __forceinline__ float2 unpack2(ull v) {
    float2 f; asm("mov.b64 {%0,%1}, %2;" : "=f"(f.x), "=f"(f.y) : "l"(v)); return f;
}
__device__ __forceinline__ float f2tf32f(float x) {
    uint32_t u; asm("cvt.rna.tf32.f32 %0, %1;" : "=r"(u) : "f"(x));
    return __uint_as_float(u);
}
__device__ __forceinline__ uint32_t smem_u32(const void* p) {
    uint32_t a; asm("{ .reg .u64 t; cvta.to.shared.u64 t, %1; cvt.u32.u64 %0, t; }" : "=r"(a) : "l"(p)); return a;
}
__device__ __forceinline__ void cpasync16(uint32_t saddr, const void* gaddr) {
    asm volatile("cp.async.cg.shared.global [%0], [%1], 16;" :: "r"(saddr), "l"(gaddr));
}
__device__ __forceinline__ void mma_tf32(float* d, const uint32_t* a, const uint32_t* b) {
    asm volatile(
        "mma.sync.aligned.m16n8k8.row.col.f32.tf32.tf32.f32 "
        "{%0,%1,%2,%3}, {%4,%5,%6,%7}, {%8,%9}, {%0,%1,%2,%3};"
        : "+f"(d[0]), "+f"(d[1]), "+f"(d[2]), "+f"(d[3])
        : "r"(a[0]), "r"(a[1]), "r"(a[2]), "r"(a[3]), "r"(b[0]), "r"(b[1]));
}

// ---------------- scratch ----------------
__device__ float g_Q[BH*L*D];
__device__ float g_K[BH*L*D];
__device__ float g_V[BH*L*D];
__device__ float g_P[BH*L*TT];
__device__ float g_AO[ROWS*HID];
__device__ float g_WT[4*HID*HID];   // tf32-rounded transposed weights
__device__ float g_X32[ROWS*HID];   // tf32-rounded x

// ---------------- rounding kernel: dst = tf32(src), float4 ----------------
__global__ __launch_bounds__(256) void round_kernel(
    const float* __restrict__ src, float* __restrict__ dst)
{
    int i = blockIdx.x * 256 + threadIdx.x;
    float4 v = ((const float4*)src)[i];
    v.x = f2tf32f(v.x); v.y = f2tf32f(v.y); v.z = f2tf32f(v.z); v.w = f2tf32f(v.w);
    ((float4*)dst)[i] = v;
}

// ---------------- W transpose + tf32 round ----------------
__global__ __launch_bounds__(256) void transpose_kernel(
    const float* __restrict__ Wsrc, float* __restrict__ Wdst)
{
    __shared__ float t[32][33];
    int x  = blockIdx.x * 32 + threadIdx.x;
    int y0 = blockIdx.y * 32 + threadIdx.y;
#pragma unroll
    for (int dy = 0; dy < 32; dy += 8)
        t[threadIdx.y + dy][threadIdx.x] = f2tf32f(Wsrc[(size_t)(y0 + dy) * HID + x]);
    __syncthreads();
    int xo  = blockIdx.y * 32 + threadIdx.x;
    int yo0 = blockIdx.x * 32 + threadIdx.y;
#pragma unroll
    for (int dy = 0; dy < 32; dy += 8)
        Wdst[(size_t)(yo0 + dy) * HID + xo] = t[threadIdx.x][threadIdx.y + dy];
}

// ---------------- tf32 mma GEMM, cp.async double-buffered, fused over W ---
#define KC 32
#define KCP 36
#define NCHUNK (HID/KC)         // 24
#define SSZ (128*KCP)           // floats per operand per stage

__global__ __launch_bounds__(256, 2) void gemm_mma_kernel(
    const float* __restrict__ A, const float* __restrict__ WTbase,
    const float* __restrict__ b0, const float* __restrict__ b1, const float* __restrict__ b2,
    float* __restrict__ o0, float* __restrict__ o1, float* __restrict__ o2,
    int nbW, int headLayout)
{
    extern __shared__ float smem[];
    const uint32_t sbase = smem_u32(smem);

    const int tid = threadIdx.x;
    const int wid = tid >> 5, lane = tid & 31;
    const int g = lane >> 2, t = lane & 3;
    const int warp_m = wid & 3;
    const int warp_n = wid >> 2;
    const int row0 = blockIdx.x * 128;
    const int by = blockIdx.y;
    const int wsel = by / nbW;
    const int col0 = (by % nbW) * 128;

    const float* WT = WTbase + (size_t)wsel * HID * HID;
    const float* bias = (wsel == 0) ? b0 : (wsel == 1 ? b1 : b2);
    float* Cout = (wsel == 0) ? o0 : (wsel == 1 ? o1 : o2);

    const int sr = tid >> 3;            // staging row (per iter +32)
    const int sv = (tid & 7) << 2;      // staging k offset

    float acc[2][8][4];
#pragma unroll
    for (int mf = 0; mf < 2; ++mf)
#pragma unroll
        for (int nf = 0; nf < 8; ++nf)
#pragma unroll
            for (int c = 0; c < 4; ++c) acc[mf][nf][c] = 0.f;

    const int mbase = warp_m * 32;
    const int nbase = warp_n * 64;

    // ---- issue one chunk's cp.async into stage s ----
    auto issue = [&](int c, int s) {
        uint32_t as = sbase + (uint32_t)(s * 2 * SSZ) * 4u;
        uint32_t bs = as + (uint32_t)SSZ * 4u;
        int k0 = c * KC;
#pragma unroll
        for (int it = 0; it < 4; ++it) {
            int r = sr + it * 32;
            uint32_t so = (uint32_t)(r * KCP + sv) * 4u;
            cpasync16(as + so, &A [(size_t)(row0 + r) * HID + k0 + sv]);
            cpasync16(bs + so, &WT[(size_t)(col0 + r) * HID + k0 + sv]);
        }
        asm volatile("cp.async.commit_group;" ::: "memory");
    };

    issue(0, 0);
    issue(1, 1);

    for (int c = 0; c < NCHUNK; ++c) {
        int s = c & 1;
        if (c < NCHUNK - 2) asm volatile("cp.async.wait_group 1;" ::: "memory");
        else                asm volatile("cp.async.wait_group 0;" ::: "memory");
        __syncthreads();

        const float* As = smem + s * 2 * SSZ;
        const float* Bs = As + SSZ;

#pragma unroll
        for (int kk = 0; kk < KC; kk += 8) {
            uint32_t bfr[8][2];
#pragma unroll
            for (int nf = 0; nf < 8; ++nf) {
                const float* bp = &Bs[(nbase + nf * 8 + g) * KCP + kk + t];
                bfr[nf][0] = __float_as_uint(bp[0]);
                bfr[nf][1] = __float_as_uint(bp[4]);
            }
            uint32_t afr[2][4];
#pragma unroll
            for (int mf = 0; mf < 2; ++mf) {
                const float* ap = &As[(mbase + mf * 16 + g) * KCP + kk + t];
                afr[mf][0] = __float_as_uint(ap[0]);
                afr[mf][1] = __float_as_uint(ap[8 * KCP]);
                afr[mf][2] = __float_as_uint(ap[4]);
                afr[mf][3] = __float_as_uint(ap[8 * KCP + 4]);
            }
#pragma unroll
            for (int mf = 0; mf < 2; ++mf)
#pragma unroll
                for (int nf = 0; nf < 8; ++nf)
                    mma_tf32(acc[mf][nf], afr[mf], bfr[nf]);
        }
        __syncthreads();
        if (c + 2 < NCHUNK) issue(c + 2, s);
    }

#pragma unroll
    for (int mf = 0; mf < 2; ++mf) {
#pragma unroll
        for (int nf = 0; nf < 8; ++nf) {
            int row_a = row0 + mbase + mf * 16 + g;
            int col_a = col0 + nbase + nf * 8 + 2 * t;
#pragma unroll
            for (int half = 0; half < 2; ++half) {
                int row = row_a + half * 8;
                float2 v;
                v.x = acc[mf][nf][2 * half]     + bias[col_a];
                v.y = acc[mf][nf][2 * half + 1] + bias[col_a + 1];
                if (headLayout) {
                    int bb2 = row >> 9, ll = row & 511, hh = col_a >> 6, dd = col_a & 63;
                    *(float2*)&Cout[(((size_t)bb2 * NH + hh) * L + ll) * D + dd] = v;
                } else {
                    *(float2*)&Cout[(size_t)row * HID + col_a] = v;
                }
            }
        }
    }
}

// ---------------- proj via mma (unchanged from R9 win) ----------------
__device__ __forceinline__ uint32_t f2tf32u(float x) {
    uint32_t u; asm("cvt.rna.tf32.f32 %0, %1;" : "=r"(u) : "f"(x)); return u;
}

__global__ __launch_bounds__(256) void proj_mma_kernel(
    const float* __restrict__ qh, const float* __restrict__ qe,
    const float* __restrict__ kh, const float* __restrict__ ke)
{
    __shared__ float As[128 * KCP];
    __shared__ float Bs[TT * KCP];

    const int tid = threadIdx.x;
    const int wid = tid >> 5, lane = tid & 31;
    const int g = lane >> 2, t = lane & 3;
    const int warp_m = wid & 3;
    const int warp_n = wid >> 2;
    const int l0 = blockIdx.x * 128;
    const int bh = blockIdx.y;
    const int h  = bh % NH;

    float acc[2][6][4];
#pragma unroll
    for (int mf = 0; mf < 2; ++mf)
#pragma unroll
        for (int nf = 0; nf < 6; ++nf)
#pragma unroll
            for (int c = 0; c < 4; ++c) acc[mf][nf][c] = 0.f;

    const int mbase = warp_m * 32;
    const int nbase = warp_n * 48;

    for (int c = 0; c < 4; ++c) {
        const float* Asrc = (c < 2 ? g_Q : g_K) + ((size_t)bh * L + l0) * D + (c & 1) * 32;
        const float* E1 = (c < 2) ? qh : kh;
        const float* E2 = (c < 2) ? qe : ke;
        const int koff = h * D + (c & 1) * 32;

#pragma unroll
        for (int it = 0; it < 4; ++it) {
            int idx = tid + it * 256;
            int r = idx >> 3, v = (idx & 7) << 2;
            float4 a = *(const float4*)&Asrc[(size_t)r * D + v];
            float* da = &As[r * KCP + v];
            da[0] = f2tf32f(a.x); da[1] = f2tf32f(a.y);
            da[2] = f2tf32f(a.z); da[3] = f2tf32f(a.w);
        }
#pragma unroll
        for (int it = 0; it < 3; ++it) {
            int idx = tid + it * 256;
            int r = idx >> 3, v = (idx & 7) << 2;
            const float* src = (r < TH) ? &E1[(size_t)r * HID + koff + v]
                                        : &E2[(size_t)(r - TH) * HID + koff + v];
            float4 b = *(const float4*)src;
            float* db = &Bs[r * KCP + v];
            db[0] = f2tf32f(b.x); db[1] = f2tf32f(b.y);
            db[2] = f2tf32f(b.z); db[3] = f2tf32f(b.w);
        }
        __syncthreads();

#pragma unroll
        for (int kk = 0; kk < KC; kk += 8) {
            uint32_t bfr[6][2];
#pragma unroll
            for (int nf = 0; nf < 6; ++nf) {
                const float* bp = &Bs[(nbase + nf * 8 + g) * KCP + kk + t];
                bfr[nf][0] = __float_as_uint(bp[0]);
                bfr[nf][1] = __float_as_uint(bp[4]);
            }
            uint32_t afr[2][4];
#pragma unroll
            for (int mf = 0; mf < 2; ++mf) {
                const float* ap = &As[(mbase + mf * 16 + g) * KCP + kk + t];
                afr[mf][0] = __float_as_uint(ap[0]);
                afr[mf][1] = __float_as_uint(ap[8 * KCP]);
                afr[mf][2] = __float_as_uint(ap[4]);
                afr[mf][3] = __float_as_uint(ap[8 * KCP + 4]);
            }
#pragma unroll
            for (int mf = 0; mf < 2; ++mf)
#pragma unroll
                for (int nf = 0; nf < 6; ++nf)
                    mma_tf32(acc[mf][nf], afr[mf], bfr[nf]);
        }
        __syncthreads();
    }

    float* Pout = g_P + ((size_t)bh * L + l0) * TT;
#pragma unroll
    for (int mf = 0; mf < 2; ++mf) {
#pragma unroll
        for (int nf = 0; nf < 6; ++nf) {
            int row_a = mbase + mf * 16 + g;
            int col_a = nbase + nf * 8 + 2 * t;
#pragma unroll
            for (int half = 0; half < 2; ++half) {
                int row = row_a + half * 8;
                float2 v;
                v.x = acc[mf][nf][2 * half];
                v.y = acc[mf][nf][2 * half + 1];
                *(float2*)&Pout[(size_t)row * TT + col_a] = v;
            }
        }
    }
}

// ---------------- attention: single-pass + 2-replica bins ----------------
#define AT_ROWS 32
#define ESS 132
#define KSTR 132
#define VSTR 68
#define BUF_FLOATS (128*VSTR)
// qs + Ps + bins(2 replicas) + es + buf + rs
#define ATT_SMEM_FLOATS (AT_ROWS*64 + AT_ROWS*TT + AT_ROWS*2*TT + AT_ROWS*ESS + BUF_FLOATS + 32)

__global__ __launch_bounds__(256) void attn_kernel(
    const int* __restrict__ hop, const int* __restrict__ edge,
    const float* __restrict__ vh, const float* __restrict__ ve)
{
    extern __shared__ float sm[];
    float* qs   = sm;                          // [32][64]
    float* Ps   = qs + AT_ROWS * 64;           // [32][96]
    float* bins = Ps + AT_ROWS * TT;           // [32][2][96]
    float* es   = bins + AT_ROWS * 2 * TT;     // [32][132]
    float* buf  = es + AT_ROWS * ESS;          // staging
    float* rs   = buf + BUF_FLOATS;            // [32]

    const int bh = blockIdx.y;
    const int bb = bh / NH, h = bh % NH;
    const int i0 = blockIdx.x * AT_ROWS;
    const int tid = threadIdx.x;
    const float scale = 0.125f;

    {
        const float* Qp = g_Q + ((size_t)bh * L + i0) * D;
        for (int idx = tid; idx < AT_ROWS * D; idx += 256) qs[idx] = Qp[idx];
        const float* Pp = g_P + ((size_t)bh * L + i0) * TT;
        for (int idx = tid; idx < AT_ROWS * TT; idx += 256) Ps[idx] = Pp[idx];
        for (int idx = tid; idx < AT_ROWS * 2 * TT; idx += 256) bins[idx] = 0.f;
    }

    const size_t hopBase = ((size_t)bb * L + i0) * L;

    const int jg = tid & 31;
    const int ig = tid >> 5;
    const int j0 = jg * 4;
    const int ib4 = ig * 4;
    const int rep = jg >> 4;        // half-warp replica select

    const int gv  = tid >> 7;
    const int t2  = tid & 127;
    const int ig2 = t2 >> 4;
    const int dg  = t2 & 15;
    const int i4  = ig2 * 4;
    const int d0  = dg * 4;

    float lsum[4] = {0.f, 0.f, 0.f, 0.f};
    ull oa[4][2];
#pragma unroll
    for (int r = 0; r < 4; ++r) { oa[r][0] = 0ull; oa[r][1] = 0ull; }

    for (int jc = 0; jc < L; jc += 128) {
        const float* Kp = g_K + ((size_t)bh * L + jc) * D;
        for (int idx4 = tid; idx4 < 2048; idx4 += 256) {
            int jj = idx4 >> 4, dd4 = (idx4 & 15) << 2;
            float4 kv = *(const float4*)&Kp[(size_t)jj * D + dd4];
            buf[(dd4 + 0) * KSTR + jj] = kv.x;
            buf[(dd4 + 1) * KSTR + jj] = kv.y;
            buf[(dd4 + 2) * KSTR + jj] = kv.z;
            buf[(dd4 + 3) * KSTR + jj] = kv.w;
        }
        __syncthreads();

        ull acc[4][2];
#pragma unroll
        for (int r = 0; r < 4; ++r) { acc[r][0] = 0ull; acc[r][1] = 0ull; }

        for (int dd = 0; dd < D; ++dd) {
            float4 kj = *(const float4*)&buf[dd * KSTR + j0];
            ull k01 = ((const ull*)&kj)[0];
            ull k23 = ((const ull*)&kj)[1];
#pragma unroll
            for (int r = 0; r < 4; ++r) {
                float qv = qs[(ib4 + r) * D + dd];
                ull qq = pack2(qv, qv);
                acc[r][0] = ffma2(qq, k01, acc[r][0]);
                acc[r][1] = ffma2(qq, k23, acc[r][1]);
            }
        }

#pragma unroll
        for (int r = 0; r < 4; ++r) {
            int i = ib4 + r;
            const int4 hp = *(const int4*)&hop [hopBase + (size_t)i * L + jc + j0];
            const int4 ep = *(const int4*)&edge[hopBase + (size_t)i * L + jc + j0];
            float2 a0 = unpack2(acc[r][0]);
            float2 a1 = unpack2(acc[r][1]);
            const float* prow = Ps + i * TT;
            float s0 = (a0.x + prow[hp.x] + prow[TH + ep.x]) * scale;
            float s1 = (a0.y + prow[hp.y] + prow[TH + ep.y]) * scale;
            float s2 = (a1.x + prow[hp.z] + prow[TH + ep.z]) * scale;
            float s3 = (a1.y + prow[hp.w] + prow[TH + ep.w]) * scale;
            float e0 = __expf(fminf(fmaxf(s0, -70.f), 70.f));
            float e1 = __expf(fminf(fmaxf(s1, -70.f), 70.f));
            float e2 = __expf(fminf(fmaxf(s2, -70.f), 70.f));
            float e3 = __expf(fminf(fmaxf(s3, -70.f), 70.f));
            float* erow = es + i * ESS + j0;
            erow[0] = e0; erow[1] = e1; erow[2] = e2; erow[3] = e3;
            lsum[r] += (e0 + e1) + (e2 + e3);
            float* brow = bins + (i * 2 + rep) * TT;
            atomicAdd(&brow[hp.x], e0);      atomicAdd(&brow[TH + ep.x], e0);
            atomicAdd(&brow[hp.y], e1);      atomicAdd(&brow[TH + ep.y], e1);
            atomicAdd(&brow[hp.z], e2);      atomicAdd(&brow[TH + ep.z], e2);
            atomicAdd(&brow[hp.w], e3);      atomicAdd(&brow[TH + ep.w], e3);
        }
        __syncthreads();

        const float* Vp = g_V + ((size_t)bh * L + jc) * D;
        for (int idx4 = tid; idx4 < 2048; idx4 += 256) {
            int jj = idx4 >> 4, dd4 = (idx4 & 15) << 2;
            *(float4*)&buf[jj * VSTR + dd4] = *(const float4*)&Vp[(size_t)jj * D + dd4];
        }
        __syncthreads();

        for (int jj = gv; jj < 128; jj += 2) {
            float4 vv = *(const float4*)&buf[jj * VSTR + d0];
            ull v01 = ((const ull*)&vv)[0];
            ull v23 = ((const ull*)&vv)[1];
#pragma unroll
            for (int r = 0; r < 4; ++r) {
                float av = es[(i4 + r) * ESS + jj];
                ull aa = pack2(av, av);
                oa[r][0] = ffma2(aa, v01, oa[r][0]);
                oa[r][1] = ffma2(aa, v23, oa[r][1]);
            }
        }
        __syncthreads();
    }

#pragma unroll
    for (int r = 0; r < 4; ++r) {
        float v = lsum[r];
#pragma unroll
        for (int off = 16; off > 0; off >>= 1) v += __shfl_xor_sync(0xffffffffu, v, off);
        if (jg == 0) rs[ib4 + r] = 1.f / v;
    }

    for (int idx = tid; idx < TT * D; idx += 256) {
        int t = idx >> 6, d2 = idx & 63;
        buf[t * VSTR + d2] = (t < TH) ? vh[(size_t)t * HID + h * D + d2]
                                      : ve[(size_t)(t - TH) * HID + h * D + d2];
    }
    __syncthreads();

    for (int t = 48 * gv; t < 48 * gv + 48; ++t) {
        float4 vv = *(const float4*)&buf[t * VSTR + d0];
        ull v01 = ((const ull*)&vv)[0];
        ull v23 = ((const ull*)&vv)[1];
#pragma unroll
        for (int r = 0; r < 4; ++r) {
            int i = i4 + r;
            float bv = bins[i * 2 * TT + t] + bins[(i * 2 + 1) * TT + t];
            ull aa = pack2(bv, bv);
            oa[r][0] = ffma2(aa, v01, oa[r][0]);
            oa[r][1] = ffma2(aa, v23, oa[r][1]);
        }
    }
    __syncthreads();

    if (gv == 1) {
#pragma unroll
        for (int r = 0; r < 4; ++r) {
            int i = i4 + r;
            float2 x0 = unpack2(oa[r][0]);
            float2 x1 = unpack2(oa[r][1]);
            *(float4*)&buf[i * VSTR + d0] = make_float4(x0.x, x0.y, x1.x, x1.y);
        }
    }
    __syncthreads();
    if (gv == 0) {
#pragma unroll
        for (int r = 0; r < 4; ++r) {
            int i = i4 + r;
            float rinv = rs[i];
            float4 ov = *(const float4*)&buf[i * VSTR + d0];
            float2 x0 = unpack2(oa[r][0]);
            float2 x1 = unpack2(oa[r][1]);
            // tf32-round AO at write: Wo GEMM stages it as-is via cp.async
            float4 res;
            res.x = f2tf32f((x0.x + ov.x) * rinv);
            res.y = f2tf32f((x0.y + ov.y) * rinv);
            res.z = f2tf32f((x1.x + ov.z) * rinv);
            res.w = f2tf32f((x1.y + ov.w) * rinv);
            *(float4*)&g_AO[((size_t)bb * L + i0 + i) * HID + h * D + d0] = res;
        }
    }
}

// --------------------------------------------------------------------------
extern "C" void kernel_launch(void* const* d_in, const int* in_sizes, int n_in,
                              void* d_out, int out_size)
{
    const float* x   = (const float*)d_in[0];
    const float* qh  = (const float*)d_in[1];
    const float* qe  = (const float*)d_in[2];
    const float* kh  = (const float*)d_in[3];
    const float* ke  = (const float*)d_in[4];
    const float* vh  = (const float*)d_in[5];
    const float* ve  = (const float*)d_in[6];
    const int*   hop = (const int*)d_in[7];
    const int*   edg = (const int*)d_in[8];
    const float* Wq = (const float*)d_in[9];   const float* bq = (const float*)d_in[10];
    const float* Wk = (const float*)d_in[11];  const float* bk = (const float*)d_in[12];
    const float* Wv = (const float*)d_in[13];  const float* bv = (const float*)d_in[14];
    const float* Wo = (const float*)d_in[15];  const float* bo = (const float*)d_in[16];
    float* out = (float*)d_out;

    float *Qp, *Kp, *Vp, *AOp, *WTp, *X32p;
    cudaGetSymbolAddress((void**)&Qp,  g_Q);
    cudaGetSymbolAddress((void**)&Kp,  g_K);
    cudaGetSymbolAddress((void**)&Vp,  g_V);
    cudaGetSymbolAddress((void**)&AOp, g_AO);
    cudaGetSymbolAddress((void**)&WTp, g_WT);
    cudaGetSymbolAddress((void**)&X32p, g_X32);

    const int attSmem  = ATT_SMEM_FLOATS * (int)sizeof(float);
    const int gemmSmem = 4 * SSZ * (int)sizeof(float);     // 2 stages x (A+B)
    cudaFuncSetAttribute(attn_kernel, cudaFuncAttributeMaxDynamicSharedMemorySize, attSmem);
    cudaFuncSetAttribute(gemm_mma_kernel, cudaFuncAttributeMaxDynamicSharedMemorySize, gemmSmem);

    dim3 tg(HID / 32, HID / 32);
    dim3 tb(32, 8);

    round_kernel<<<ROWS * HID / 1024, 256>>>(x, X32p);
    transpose_kernel<<<tg, tb>>>(Wq, WTp);
    transpose_kernel<<<tg, tb>>>(Wk, WTp + (size_t)HID * HID);
    transpose_kernel<<<tg, tb>>>(Wv, WTp + 2 * (size_t)HID * HID);
    transpose_kernel<<<tg, tb>>>(Wo, WTp + 3 * (size_t)HID * HID);

    // fused QKV: grid.y = 3 weights x 6 col-blocks
    gemm_mma_kernel<<<dim3(ROWS / 128, 18), 256, gemmSmem>>>(
        X32p, WTp, bq, bk, bv, Qp, Kp, Vp, 6, 1);

    proj_mma_kernel<<<dim3(L / 128, BH), 256>>>(qh, qe, kh, ke);
    attn_kernel<<<dim3(L / AT_ROWS, BH), 256, attSmem>>>(hop, edg, vh, ve);

    gemm_mma_kernel<<<dim3(ROWS / 128, 6), 256, gemmSmem>>>(
        AOp, WTp + 3 * (size_t)HID * HID, bo, bo, bo, out, out, out, 6, 0);
}

// round 13
// speedup vs baseline: 3.8382x; 1.1398x over previous
#include <cuda_runtime.h>
#include <cstdint>

#define B 8
#define L 512
#define HID 768
#define NH 12
#define D 64
#define TH 32
#define TE 64
#define TT 96
#define BH (B*NH)
#define ROWS (B*L)

typedef unsigned long long ull;

__device__ __forceinline__ float f2tf32f(float x) {
    uint32_t u; asm("cvt.rna.tf32.f32 %0, %1;" : "=r"(u) : "f"(x));
    return __uint_as_float(u);
}
__device__ __forceinline__ uint32_t smem_u32(const void* p) {
    uint32_t a; asm("{ .reg .u64 t; cvta.to.shared.u64 t, %1; cvt.u32.u64 %0, t; }" : "=r"(a) : "l"(p)); return a;
}
__device__ __forceinline__ void cpasync16(uint32_t saddr, const void* gaddr) {
    asm volatile("cp.async.cg.shared.global [%0], [%1], 16;" :: "r"(saddr), "l"(gaddr));
}
__device__ __forceinline__ void mma_tf32(float* d, const uint32_t* a, const uint32_t* b) {
    asm volatile(
        "mma.sync.aligned.m16n8k8.row.col.f32.tf32.tf32.f32 "
        "{%0,%1,%2,%3}, {%4,%5,%6,%7}, {%8,%9}, {%0,%1,%2,%3};"
        : "+f"(d[0]), "+f"(d[1]), "+f"(d[2]), "+f"(d[3])
        : "r"(a[0]), "r"(a[1]), "r"(a[2]), "r"(a[3]), "r"(b[0]), "r"(b[1]));
}

// ---------------- scratch ----------------
__device__ float g_Q[BH*L*D];
__device__ float g_K[BH*L*D];
__device__ float g_V[BH*L*D];
__device__ float g_P[BH*L*TT];
__device__ float g_AO[ROWS*HID];
__device__ float g_WT[4*HID*HID];
__device__ float g_X32[ROWS*HID];

// ---------------- rounding kernel ----------------
__global__ __launch_bounds__(256) void round_kernel(
    const float* __restrict__ src, float* __restrict__ dst)
{
    int i = blockIdx.x * 256 + threadIdx.x;
    float4 v = ((const float4*)src)[i];
    v.x = f2tf32f(v.x); v.y = f2tf32f(v.y); v.z = f2tf32f(v.z); v.w = f2tf32f(v.w);
    ((float4*)dst)[i] = v;
}

// ---------------- W transpose + tf32 round ----------------
__global__ __launch_bounds__(256) void transpose_kernel(
    const float* __restrict__ Wsrc, float* __restrict__ Wdst)
{
    __shared__ float t[32][33];
    int x  = blockIdx.x * 32 + threadIdx.x;
    int y0 = blockIdx.y * 32 + threadIdx.y;
#pragma unroll
    for (int dy = 0; dy < 32; dy += 8)
        t[threadIdx.y + dy][threadIdx.x] = f2tf32f(Wsrc[(size_t)(y0 + dy) * HID + x]);
    __syncthreads();
    int xo  = blockIdx.y * 32 + threadIdx.x;
    int yo0 = blockIdx.x * 32 + threadIdx.y;
#pragma unroll
    for (int dy = 0; dy < 32; dy += 8)
        Wdst[(size_t)(yo0 + dy) * HID + xo] = t[threadIdx.x][threadIdx.y + dy];
}

// ---------------- tf32 mma GEMM, cp.async 2-stage, fused over W (R11) -----
#define KC 32
#define KCP 36
#define NCHUNK (HID/KC)
#define SSZ (128*KCP)

__global__ __launch_bounds__(256, 2) void gemm_mma_kernel(
    const float* __restrict__ A, const float* __restrict__ WTbase,
    const float* __restrict__ b0, const float* __restrict__ b1, const float* __restrict__ b2,
    float* __restrict__ o0, float* __restrict__ o1, float* __restrict__ o2,
    int nbW, int headLayout)
{
    extern __shared__ float smem[];
    const uint32_t sbase = smem_u32(smem);

    const int tid = threadIdx.x;
    const int wid = tid >> 5, lane = tid & 31;
    const int g = lane >> 2, t = lane & 3;
    const int warp_m = wid & 3;
    const int warp_n = wid >> 2;
    const int row0 = blockIdx.x * 128;
    const int by = blockIdx.y;
    const int wsel = by / nbW;
    const int col0 = (by % nbW) * 128;

    const float* WT = WTbase + (size_t)wsel * HID * HID;
    const float* bias = (wsel == 0) ? b0 : (wsel == 1 ? b1 : b2);
    float* Cout = (wsel == 0) ? o0 : (wsel == 1 ? o1 : o2);

    const int sr = tid >> 3;
    const int sv = (tid & 7) << 2;

    float acc[2][8][4];
#pragma unroll
    for (int mf = 0; mf < 2; ++mf)
#pragma unroll
        for (int nf = 0; nf < 8; ++nf)
#pragma unroll
            for (int c = 0; c < 4; ++c) acc[mf][nf][c] = 0.f;

    const int mbase = warp_m * 32;
    const int nbase = warp_n * 64;

    auto issue = [&](int c, int s) {
        uint32_t as = sbase + (uint32_t)(s * 2 * SSZ) * 4u;
        uint32_t bs = as + (uint32_t)SSZ * 4u;
        int k0 = c * KC;
#pragma unroll
        for (int it = 0; it < 4; ++it) {
            int r = sr + it * 32;
            uint32_t so = (uint32_t)(r * KCP + sv) * 4u;
            cpasync16(as + so, &A [(size_t)(row0 + r) * HID + k0 + sv]);
            cpasync16(bs + so, &WT[(size_t)(col0 + r) * HID + k0 + sv]);
        }
        asm volatile("cp.async.commit_group;" ::: "memory");
    };

    issue(0, 0);
    issue(1, 1);

    for (int c = 0; c < NCHUNK; ++c) {
        int s = c & 1;
        if (c < NCHUNK - 2) asm volatile("cp.async.wait_group 1;" ::: "memory");
        else                asm volatile("cp.async.wait_group 0;" ::: "memory");
        __syncthreads();

        const float* As = smem + s * 2 * SSZ;
        const float* Bs = As + SSZ;

#pragma unroll
        for (int kk = 0; kk < KC; kk += 8) {
            uint32_t bfr[8][2];
#pragma unroll
            for (int nf = 0; nf < 8; ++nf) {
                const float* bp = &Bs[(nbase + nf * 8 + g) * KCP + kk + t];
                bfr[nf][0] = __float_as_uint(bp[0]);
                bfr[nf][1] = __float_as_uint(bp[4]);
            }
            uint32_t afr[2][4];
#pragma unroll
            for (int mf = 0; mf < 2; ++mf) {
                const float* ap = &As[(mbase + mf * 16 + g) * KCP + kk + t];
                afr[mf][0] = __float_as_uint(ap[0]);
                afr[mf][1] = __float_as_uint(ap[8 * KCP]);
                afr[mf][2] = __float_as_uint(ap[4]);
                afr[mf][3] = __float_as_uint(ap[8 * KCP + 4]);
            }
#pragma unroll
            for (int mf = 0; mf < 2; ++mf)
#pragma unroll
                for (int nf = 0; nf < 8; ++nf)
                    mma_tf32(acc[mf][nf], afr[mf], bfr[nf]);
        }
        __syncthreads();
        if (c + 2 < NCHUNK) issue(c + 2, s);
    }

#pragma unroll
    for (int mf = 0; mf < 2; ++mf) {
#pragma unroll
        for (int nf = 0; nf < 8; ++nf) {
            int row_a = row0 + mbase + mf * 16 + g;
            int col_a = col0 + nbase + nf * 8 + 2 * t;
#pragma unroll
            for (int half = 0; half < 2; ++half) {
                int row = row_a + half * 8;
                float2 v;
                v.x = acc[mf][nf][2 * half]     + bias[col_a];
                v.y = acc[mf][nf][2 * half + 1] + bias[col_a + 1];
                if (headLayout) {
                    int bb2 = row >> 9, ll = row & 511, hh = col_a >> 6, dd = col_a & 63;
                    *(float2*)&Cout[(((size_t)bb2 * NH + hh) * L + ll) * D + dd] = v;
                } else {
                    *(float2*)&Cout[(size_t)row * HID + col_a] = v;
                }
            }
        }
    }
}

// ---------------- proj via mma (R9 win, unchanged) ----------------
__global__ __launch_bounds__(256) void proj_mma_kernel(
    const float* __restrict__ qh, const float* __restrict__ qe,
    const float* __restrict__ kh, const float* __restrict__ ke)
{
    __shared__ float As[128 * KCP];
    __shared__ float Bs[TT * KCP];

    const int tid = threadIdx.x;
    const int wid = tid >> 5, lane = tid & 31;
    const int g = lane >> 2, t = lane & 3;
    const int warp_m = wid & 3;
    const int warp_n = wid >> 2;
    const int l0 = blockIdx.x * 128;
    const int bh = blockIdx.y;
    const int h  = bh % NH;

    float acc[2][6][4];
#pragma unroll
    for (int mf = 0; mf < 2; ++mf)
#pragma unroll
        for (int nf = 0; nf < 6; ++nf)
#pragma unroll
            for (int c = 0; c < 4; ++c) acc[mf][nf][c] = 0.f;

    const int mbase = warp_m * 32;
    const int nbase = warp_n * 48;

    for (int c = 0; c < 4; ++c) {
        const float* Asrc = (c < 2 ? g_Q : g_K) + ((size_t)bh * L + l0) * D + (c & 1) * 32;
        const float* E1 = (c < 2) ? qh : kh;
        const float* E2 = (c < 2) ? qe : ke;
        const int koff = h * D + (c & 1) * 32;

#pragma unroll
        for (int it = 0; it < 4; ++it) {
            int idx = tid + it * 256;
            int r = idx >> 3, v = (idx & 7) << 2;
            float4 a = *(const float4*)&Asrc[(size_t)r * D + v];
            float* da = &As[r * KCP + v];
            da[0] = f2tf32f(a.x); da[1] = f2tf32f(a.y);
            da[2] = f2tf32f(a.z); da[3] = f2tf32f(a.w);
        }
#pragma unroll
        for (int it = 0; it < 3; ++it) {
            int idx = tid + it * 256;
            int r = idx >> 3, v = (idx & 7) << 2;
            const float* src = (r < TH) ? &E1[(size_t)r * HID + koff + v]
                                        : &E2[(size_t)(r - TH) * HID + koff + v];
            float4 b = *(const float4*)src;
            float* db = &Bs[r * KCP + v];
            db[0] = f2tf32f(b.x); db[1] = f2tf32f(b.y);
            db[2] = f2tf32f(b.z); db[3] = f2tf32f(b.w);
        }
        __syncthreads();

#pragma unroll
        for (int kk = 0; kk < KC; kk += 8) {
            uint32_t bfr[6][2];
#pragma unroll
            for (int nf = 0; nf < 6; ++nf) {
                const float* bp = &Bs[(nbase + nf * 8 + g) * KCP + kk + t];
                bfr[nf][0] = __float_as_uint(bp[0]);
                bfr[nf][1] = __float_as_uint(bp[4]);
            }
            uint32_t afr[2][4];
#pragma unroll
            for (int mf = 0; mf < 2; ++mf) {
                const float* ap = &As[(mbase + mf * 16 + g) * KCP + kk + t];
                afr[mf][0] = __float_as_uint(ap[0]);
                afr[mf][1] = __float_as_uint(ap[8 * KCP]);
                afr[mf][2] = __float_as_uint(ap[4]);
                afr[mf][3] = __float_as_uint(ap[8 * KCP + 4]);
            }
#pragma unroll
            for (int mf = 0; mf < 2; ++mf)
#pragma unroll
                for (int nf = 0; nf < 6; ++nf)
                    mma_tf32(acc[mf][nf], afr[mf], bfr[nf]);
        }
        __syncthreads();
    }

    float* Pout = g_P + ((size_t)bh * L + l0) * TT;
#pragma unroll
    for (int mf = 0; mf < 2; ++mf) {
#pragma unroll
        for (int nf = 0; nf < 6; ++nf) {
            int row_a = mbase + mf * 16 + g;
            int col_a = nbase + nf * 8 + 2 * t;
#pragma unroll
            for (int half = 0; half < 2; ++half) {
                int row = row_a + half * 8;
                float2 v;
                v.x = acc[mf][nf][2 * half];
                v.y = acc[mf][nf][2 * half + 1];
                *(float2*)&Pout[(size_t)row * TT + col_a] = v;
            }
        }
    }
}

// ---------------- attention: all dense phases on mma ----------------
#define AT_ROWS 32
#define QS_STR 68       // == 4 mod 32
#define KB_STR 68
#define VT_STR 132
#define ES_STR 132
#define BIN_STR 100
// qs + Ps + bins(2 rep) + es + buf + rs
#define ATT_SMEM_FLOATS (AT_ROWS*QS_STR + AT_ROWS*TT + AT_ROWS*2*BIN_STR + AT_ROWS*ES_STR + 128*KB_STR + 32)

__global__ __launch_bounds__(256) void attn_kernel(
    const int* __restrict__ hop, const int* __restrict__ edge,
    const float* __restrict__ vh, const float* __restrict__ ve)
{
    extern __shared__ float sm[];
    float* qs   = sm;                            // [32][68] tf32 Q
    float* Ps   = qs + AT_ROWS * QS_STR;         // [32][96]
    float* bins = Ps + AT_ROWS * TT;             // [32][2][100]
    float* es   = bins + AT_ROWS * 2 * BIN_STR;  // [32][132] tf32 e
    float* buf  = es + AT_ROWS * ES_STR;         // [128][68] K rows / [64][132] V^T / [64][100] VE
    float* rs   = buf + 128 * KB_STR;            // [32]
    float* binsC = es;                           // overlay after loop: [32][100]

    const int bh = blockIdx.y;
    const int bb = bh / NH, h = bh % NH;
    const int i0 = blockIdx.x * AT_ROWS;
    const int tid = threadIdx.x;
    const int wid = tid >> 5, lane = tid & 31;
    const int g = lane >> 2, t = lane & 3;
    const float scale = 0.125f;

    {
        const float* Qp = g_Q + ((size_t)bh * L + i0) * D;
        for (int idx = tid; idx < AT_ROWS * D; idx += 256) {
            int row = idx >> 6, dd = idx & 63;
            qs[row * QS_STR + dd] = f2tf32f(Qp[idx]);
        }
        const float* Pp = g_P + ((size_t)bh * L + i0) * TT;
        for (int idx = tid; idx < AT_ROWS * TT; idx += 256) Ps[idx] = Pp[idx];
        for (int idx = tid; idx < AT_ROWS * 2 * BIN_STR; idx += 256) bins[idx] = 0.f;
        if (tid < 32) rs[tid] = 0.f;
    }
    __syncthreads();

    const size_t hopBase = ((size_t)bb * L + i0) * L;
    const int nsc = wid * 16;       // score col base (16 cols/warp)
    const int nav = wid * 8;        // output d base (8 cols/warp)
    const int rep = wid & 1;

    float oacc[2][4];
#pragma unroll
    for (int mf = 0; mf < 2; ++mf)
#pragma unroll
        for (int c = 0; c < 4; ++c) oacc[mf][c] = 0.f;
    float lsum[4] = {0.f, 0.f, 0.f, 0.f};   // rows g, g+8, 16+g, 24+g

    for (int jc = 0; jc < L; jc += 128) {
        // ---- stage K chunk rows (tf32): buf[j][d], stride 68 ----
        {
            const float* Kp = g_K + ((size_t)bh * L + jc) * D;
            for (int idx4 = tid; idx4 < 2048; idx4 += 256) {
                int jj = idx4 >> 4, dd4 = (idx4 & 15) << 2;
                float4 kv = *(const float4*)&Kp[(size_t)jj * D + dd4];
                kv.x = f2tf32f(kv.x); kv.y = f2tf32f(kv.y);
                kv.z = f2tf32f(kv.z); kv.w = f2tf32f(kv.w);
                *(float4*)&buf[jj * KB_STR + dd4] = kv;
            }
        }
        __syncthreads();

        // ---- scores mma: S[32][16 cols of this warp] ----
        float sacc[2][2][4];
#pragma unroll
        for (int mf = 0; mf < 2; ++mf)
#pragma unroll
            for (int nf = 0; nf < 2; ++nf)
#pragma unroll
                for (int c = 0; c < 4; ++c) sacc[mf][nf][c] = 0.f;

#pragma unroll
        for (int ks = 0; ks < 8; ++ks) {
            int kk = ks * 8;
            uint32_t afr[2][4];
#pragma unroll
            for (int mf = 0; mf < 2; ++mf) {
                const float* ap = &qs[(mf * 16 + g) * QS_STR + kk + t];
                afr[mf][0] = __float_as_uint(ap[0]);
                afr[mf][1] = __float_as_uint(ap[8 * QS_STR]);
                afr[mf][2] = __float_as_uint(ap[4]);
                afr[mf][3] = __float_as_uint(ap[8 * QS_STR + 4]);
            }
            uint32_t bfr[2][2];
#pragma unroll
            for (int nf = 0; nf < 2; ++nf) {
                const float* bp = &buf[(nsc + nf * 8 + g) * KB_STR + kk + t];
                bfr[nf][0] = __float_as_uint(bp[0]);
                bfr[nf][1] = __float_as_uint(bp[4]);
            }
#pragma unroll
            for (int mf = 0; mf < 2; ++mf)
#pragma unroll
                for (int nf = 0; nf < 2; ++nf)
                    mma_tf32(sacc[mf][nf], afr[mf], bfr[nf]);
        }

        // ---- bias gather + exp + es store + bin scatter ----
#pragma unroll
        for (int mf = 0; mf < 2; ++mf) {
#pragma unroll
            for (int nf = 0; nf < 2; ++nf) {
                int jl = nsc + nf * 8 + 2 * t;
                size_t jbase = hopBase + jc + jl;
#pragma unroll
                for (int half = 0; half < 2; ++half) {
                    int i = mf * 16 + half * 8 + g;
                    const int2 hp = *(const int2*)&hop [jbase + (size_t)i * L];
                    const int2 ep = *(const int2*)&edge[jbase + (size_t)i * L];
                    const float* prow = Ps + i * TT;
                    float s0 = (sacc[mf][nf][2*half]   + prow[hp.x] + prow[TH + ep.x]) * scale;
                    float s1 = (sacc[mf][nf][2*half+1] + prow[hp.y] + prow[TH + ep.y]) * scale;
                    float e0 = __expf(fminf(fmaxf(s0, -70.f), 70.f));
                    float e1 = __expf(fminf(fmaxf(s1, -70.f), 70.f));
                    float2 ev = make_float2(f2tf32f(e0), f2tf32f(e1));
                    *(float2*)&es[i * ES_STR + jl] = ev;
                    lsum[mf * 2 + half] += e0 + e1;
                    float* brow = bins + (i * 2 + rep) * BIN_STR;
                    atomicAdd(&brow[hp.x], e0);  atomicAdd(&brow[TH + ep.x], e0);
                    atomicAdd(&brow[hp.y], e1);  atomicAdd(&brow[TH + ep.y], e1);
                }
            }
        }
        __syncthreads();   // es complete; buf (K) free

        // ---- stage V^T (tf32): buf[d][j], stride 132 ----
        {
            const float* Vp = g_V + ((size_t)bh * L + jc) * D;
            for (int idx4 = tid; idx4 < 2048; idx4 += 256) {
                int jj = idx4 >> 4, dd4 = (idx4 & 15) << 2;
                float4 vv = *(const float4*)&Vp[(size_t)jj * D + dd4];
                buf[(dd4 + 0) * VT_STR + jj] = f2tf32f(vv.x);
                buf[(dd4 + 1) * VT_STR + jj] = f2tf32f(vv.y);
                buf[(dd4 + 2) * VT_STR + jj] = f2tf32f(vv.z);
                buf[(dd4 + 3) * VT_STR + jj] = f2tf32f(vv.w);
            }
        }
        __syncthreads();

        // ---- AV mma: O[32][8 cols of this warp] += E[32][128] @ V ----
#pragma unroll
        for (int ks = 0; ks < 16; ++ks) {
            int kk = ks * 8;
            uint32_t bfr[2];
            {
                const float* bp = &buf[(nav + g) * VT_STR + kk + t];
                bfr[0] = __float_as_uint(bp[0]);
                bfr[1] = __float_as_uint(bp[4]);
            }
#pragma unroll
            for (int mf = 0; mf < 2; ++mf) {
                uint32_t afr[4];
                const float* ap = &es[(mf * 16 + g) * ES_STR + kk + t];
                afr[0] = __float_as_uint(ap[0]);
                afr[1] = __float_as_uint(ap[8 * ES_STR]);
                afr[2] = __float_as_uint(ap[4]);
                afr[3] = __float_as_uint(ap[8 * ES_STR + 4]);
                mma_tf32(oacc[mf], afr, bfr);
            }
        }
        __syncthreads();   // es + buf free for next chunk
    }

    // ---- row sums ----
    atomicAdd(&rs[g],      lsum[0]);
    atomicAdd(&rs[g + 8],  lsum[1]);
    atomicAdd(&rs[16 + g], lsum[2]);
    atomicAdd(&rs[24 + g], lsum[3]);
    __syncthreads();

    // ---- combine + round bins -> binsC (es region); stage VE (buf region) ----
    for (int idx = tid; idx < AT_ROWS * TT; idx += 256) {
        int row = idx / TT, tt = idx % TT;
        binsC[row * BIN_STR + tt] =
            f2tf32f(bins[(row * 2) * BIN_STR + tt] + bins[(row * 2 + 1) * BIN_STR + tt]);
    }
    for (int idx = tid; idx < TT * D; idx += 256) {
        int tt = idx >> 6, d2 = idx & 63;
        float v = (tt < TH) ? vh[(size_t)tt * HID + h * D + d2]
                            : ve[(size_t)(tt - TH) * HID + h * D + d2];
        buf[d2 * BIN_STR + tt] = f2tf32f(v);
    }
    __syncthreads();

    // ---- bins x VE mma (k = 96) ----
#pragma unroll
    for (int ks = 0; ks < 12; ++ks) {
        int kk = ks * 8;
        uint32_t bfr[2];
        {
            const float* bp = &buf[(nav + g) * BIN_STR + kk + t];
            bfr[0] = __float_as_uint(bp[0]);
            bfr[1] = __float_as_uint(bp[4]);
        }
#pragma unroll
        for (int mf = 0; mf < 2; ++mf) {
            uint32_t afr[4];
            const float* ap = &binsC[(mf * 16 + g) * BIN_STR + kk + t];
            afr[0] = __float_as_uint(ap[0]);
            afr[1] = __float_as_uint(ap[8 * BIN_STR]);
            afr[2] = __float_as_uint(ap[4]);
            afr[3] = __float_as_uint(ap[8 * BIN_STR + 4]);
            mma_tf32(oacc[mf], afr, bfr);
        }
    }

    // ---- normalize + write (tf32-rounded for the Wo GEMM) ----
#pragma unroll
    for (int mf = 0; mf < 2; ++mf) {
#pragma unroll
        for (int half = 0; half < 2; ++half) {
            int i = mf * 16 + half * 8 + g;
            float rinv = 1.f / rs[i];
            float2 v;
            v.x = f2tf32f(oacc[mf][2 * half]     * rinv);
            v.y = f2tf32f(oacc[mf][2 * half + 1] * rinv);
            *(float2*)&g_AO[((size_t)bb * L + i0 + i) * HID + h * D + nav + 2 * t] = v;
        }
    }
}

// --------------------------------------------------------------------------
extern "C" void kernel_launch(void* const* d_in, const int* in_sizes, int n_in,
                              void* d_out, int out_size)
{
    const float* x   = (const float*)d_in[0];
    const float* qh  = (const float*)d_in[1];
    const float* qe  = (const float*)d_in[2];
    const float* kh  = (const float*)d_in[3];
    const float* ke  = (const float*)d_in[4];
    const float* vh  = (const float*)d_in[5];
    const float* ve  = (const float*)d_in[6];
    const int*   hop = (const int*)d_in[7];
    const int*   edg = (const int*)d_in[8];
    const float* Wq = (const float*)d_in[9];   const float* bq = (const float*)d_in[10];
    const float* Wk = (const float*)d_in[11];  const float* bk = (const float*)d_in[12];
    const float* Wv = (const float*)d_in[13];  const float* bv = (const float*)d_in[14];
    const float* Wo = (const float*)d_in[15];  const float* bo = (const float*)d_in[16];
    float* out = (float*)d_out;

    float *Qp, *Kp, *Vp, *AOp, *WTp, *X32p;
    cudaGetSymbolAddress((void**)&Qp,  g_Q);
    cudaGetSymbolAddress((void**)&Kp,  g_K);
    cudaGetSymbolAddress((void**)&Vp,  g_V);
    cudaGetSymbolAddress((void**)&AOp, g_AO);
    cudaGetSymbolAddress((void**)&WTp, g_WT);
    cudaGetSymbolAddress((void**)&X32p, g_X32);

    const int attSmem  = ATT_SMEM_FLOATS * (int)sizeof(float);
    const int gemmSmem = 4 * SSZ * (int)sizeof(float);
    cudaFuncSetAttribute(attn_kernel, cudaFuncAttributeMaxDynamicSharedMemorySize, attSmem);
    cudaFuncSetAttribute(gemm_mma_kernel, cudaFuncAttributeMaxDynamicSharedMemorySize, gemmSmem);

    dim3 tg(HID / 32, HID / 32);
    dim3 tb(32, 8);

    round_kernel<<<ROWS * HID / 1024, 256>>>(x, X32p);
    transpose_kernel<<<tg, tb>>>(Wq, WTp);
    transpose_kernel<<<tg, tb>>>(Wk, WTp + (size_t)HID * HID);
    transpose_kernel<<<tg, tb>>>(Wv, WTp + 2 * (size_t)HID * HID);
    transpose_kernel<<<tg, tb>>>(Wo, WTp + 3 * (size_t)HID * HID);

    gemm_mma_kernel<<<dim3(ROWS / 128, 18), 256, gemmSmem>>>(
        X32p, WTp, bq, bk, bv, Qp, Kp, Vp, 6, 1);

    proj_mma_kernel<<<dim3(L / 128, BH), 256>>>(qh, qe, kh, ke);
    attn_kernel<<<dim3(L / AT_ROWS, BH), 256, attSmem>>>(hop, edg, vh, ve);

    gemm_mma_kernel<<<dim3(ROWS / 128, 6), 256, gemmSmem>>>(
        AOp, WTp + 3 * (size_t)HID * HID, bo, bo, bo, out, out, out, 6, 0);
}

// round 14
// speedup vs baseline: 3.9545x; 1.0303x over previous
#include <cuda_runtime.h>
#include <cstdint>

#define B 8
#define L 512
#define HID 768
#define NH 12
#define D 64
#define TH 32
#define TE 64
#define TT 96
#define BH (B*NH)
#define ROWS (B*L)

typedef unsigned long long ull;

__device__ __forceinline__ float f2tf32f(float x) {
    uint32_t u; asm("cvt.rna.tf32.f32 %0, %1;" : "=r"(u) : "f"(x));
    return __uint_as_float(u);
}
__device__ __forceinline__ uint32_t smem_u32(const void* p) {
    uint32_t a; asm("{ .reg .u64 t; cvta.to.shared.u64 t, %1; cvt.u32.u64 %0, t; }" : "=r"(a) : "l"(p)); return a;
}
__device__ __forceinline__ void cpasync16(uint32_t saddr, const void* gaddr) {
    asm volatile("cp.async.cg.shared.global [%0], [%1], 16;" :: "r"(saddr), "l"(gaddr));
}
__device__ __forceinline__ void mma_tf32(float* d, const uint32_t* a, const uint32_t* b) {
    asm volatile(
        "mma.sync.aligned.m16n8k8.row.col.f32.tf32.tf32.f32 "
        "{%0,%1,%2,%3}, {%4,%5,%6,%7}, {%8,%9}, {%0,%1,%2,%3};"
        : "+f"(d[0]), "+f"(d[1]), "+f"(d[2]), "+f"(d[3])
        : "r"(a[0]), "r"(a[1]), "r"(a[2]), "r"(a[3]), "r"(b[0]), "r"(b[1]));
}

// ---------------- scratch ----------------
__device__ float g_Q[BH*L*D];
__device__ float g_K[BH*L*D];
__device__ float g_V[BH*L*D];
__device__ float g_P[BH*L*TT];
__device__ float g_AO[ROWS*HID];
__device__ float g_WT[4*HID*HID];
__device__ float g_X32[ROWS*HID];

// ---------------- rounding kernel ----------------
__global__ __launch_bounds__(256) void round_kernel(
    const float* __restrict__ src, float* __restrict__ dst)
{
    int i = blockIdx.x * 256 + threadIdx.x;
    float4 v = ((const float4*)src)[i];
    v.x = f2tf32f(v.x); v.y = f2tf32f(v.y); v.z = f2tf32f(v.z); v.w = f2tf32f(v.w);
    ((float4*)dst)[i] = v;
}

// ---------------- fused W transposes (+tf32 round), blockIdx.z selects W ---
__global__ __launch_bounds__(256) void transpose4_kernel(
    const float* __restrict__ W0, const float* __restrict__ W1,
    const float* __restrict__ W2, const float* __restrict__ W3,
    float* __restrict__ Wdst)
{
    __shared__ float t[32][33];
    const float* Wsrc = (blockIdx.z == 0) ? W0 : (blockIdx.z == 1) ? W1
                       : (blockIdx.z == 2) ? W2 : W3;
    float* Wout = Wdst + (size_t)blockIdx.z * HID * HID;
    int x  = blockIdx.x * 32 + threadIdx.x;
    int y0 = blockIdx.y * 32 + threadIdx.y;
#pragma unroll
    for (int dy = 0; dy < 32; dy += 8)
        t[threadIdx.y + dy][threadIdx.x] = f2tf32f(Wsrc[(size_t)(y0 + dy) * HID + x]);
    __syncthreads();
    int xo  = blockIdx.y * 32 + threadIdx.x;
    int yo0 = blockIdx.x * 32 + threadIdx.y;
#pragma unroll
    for (int dy = 0; dy < 32; dy += 8)
        Wout[(size_t)(yo0 + dy) * HID + xo] = t[threadIdx.x][threadIdx.y + dy];
}

// ---------------- tf32 mma GEMM, cp.async 2-stage, fused over W -----------
#define KC 32
#define KCP 36
#define NCHUNK (HID/KC)
#define SSZ (128*KCP)

__global__ __launch_bounds__(256, 2) void gemm_mma_kernel(
    const float* __restrict__ A, const float* __restrict__ WTbase,
    const float* __restrict__ b0, const float* __restrict__ b1, const float* __restrict__ b2,
    float* __restrict__ o0, float* __restrict__ o1, float* __restrict__ o2,
    int nbW, int headLayout)
{
    extern __shared__ float smem[];
    const uint32_t sbase = smem_u32(smem);

    const int tid = threadIdx.x;
    const int wid = tid >> 5, lane = tid & 31;
    const int g = lane >> 2, t = lane & 3;
    const int warp_m = wid & 3;
    const int warp_n = wid >> 2;
    const int row0 = blockIdx.x * 128;
    const int by = blockIdx.y;
    const int wsel = by / nbW;
    const int col0 = (by % nbW) * 128;

    const float* WT = WTbase + (size_t)wsel * HID * HID;
    const float* bias = (wsel == 0) ? b0 : (wsel == 1 ? b1 : b2);
    float* Cout = (wsel == 0) ? o0 : (wsel == 1 ? o1 : o2);

    const int sr = tid >> 3;
    const int sv = (tid & 7) << 2;

    float acc[2][8][4];
#pragma unroll
    for (int mf = 0; mf < 2; ++mf)
#pragma unroll
        for (int nf = 0; nf < 8; ++nf)
#pragma unroll
            for (int c = 0; c < 4; ++c) acc[mf][nf][c] = 0.f;

    const int mbase = warp_m * 32;
    const int nbase = warp_n * 64;

    auto issue = [&](int c, int s) {
        uint32_t as = sbase + (uint32_t)(s * 2 * SSZ) * 4u;
        uint32_t bs = as + (uint32_t)SSZ * 4u;
        int k0 = c * KC;
#pragma unroll
        for (int it = 0; it < 4; ++it) {
            int r = sr + it * 32;
            uint32_t so = (uint32_t)(r * KCP + sv) * 4u;
            cpasync16(as + so, &A [(size_t)(row0 + r) * HID + k0 + sv]);
            cpasync16(bs + so, &WT[(size_t)(col0 + r) * HID + k0 + sv]);
        }
        asm volatile("cp.async.commit_group;" ::: "memory");
    };

    issue(0, 0);
    issue(1, 1);

    for (int c = 0; c < NCHUNK; ++c) {
        int s = c & 1;
        if (c < NCHUNK - 2) asm volatile("cp.async.wait_group 1;" ::: "memory");
        else                asm volatile("cp.async.wait_group 0;" ::: "memory");
        __syncthreads();

        const float* As = smem + s * 2 * SSZ;
        const float* Bs = As + SSZ;

#pragma unroll
        for (int kk = 0; kk < KC; kk += 8) {
            uint32_t bfr[8][2];
#pragma unroll
            for (int nf = 0; nf < 8; ++nf) {
                const float* bp = &Bs[(nbase + nf * 8 + g) * KCP + kk + t];
                bfr[nf][0] = __float_as_uint(bp[0]);
                bfr[nf][1] = __float_as_uint(bp[4]);
            }
            uint32_t afr[2][4];
#pragma unroll
            for (int mf = 0; mf < 2; ++mf) {
                const float* ap = &As[(mbase + mf * 16 + g) * KCP + kk + t];
                afr[mf][0] = __float_as_uint(ap[0]);
                afr[mf][1] = __float_as_uint(ap[8 * KCP]);
                afr[mf][2] = __float_as_uint(ap[4]);
                afr[mf][3] = __float_as_uint(ap[8 * KCP + 4]);
            }
#pragma unroll
            for (int mf = 0; mf < 2; ++mf)
#pragma unroll
                for (int nf = 0; nf < 8; ++nf)
                    mma_tf32(acc[mf][nf], afr[mf], bfr[nf]);
        }
        __syncthreads();
        if (c + 2 < NCHUNK) issue(c + 2, s);
    }

#pragma unroll
    for (int mf = 0; mf < 2; ++mf) {
#pragma unroll
        for (int nf = 0; nf < 8; ++nf) {
            int row_a = row0 + mbase + mf * 16 + g;
            int col_a = col0 + nbase + nf * 8 + 2 * t;
#pragma unroll
            for (int half = 0; half < 2; ++half) {
                int row = row_a + half * 8;
                float2 v;
                v.x = acc[mf][nf][2 * half]     + bias[col_a];
                v.y = acc[mf][nf][2 * half + 1] + bias[col_a + 1];
                if (headLayout) {
                    int bb2 = row >> 9, ll = row & 511, hh = col_a >> 6, dd = col_a & 63;
                    *(float2*)&Cout[(((size_t)bb2 * NH + hh) * L + ll) * D + dd] = v;
                } else {
                    *(float2*)&Cout[(size_t)row * HID + col_a] = v;
                }
            }
        }
    }
}

// ---------------- proj via mma (R9 win, unchanged) ----------------
__global__ __launch_bounds__(256) void proj_mma_kernel(
    const float* __restrict__ qh, const float* __restrict__ qe,
    const float* __restrict__ kh, const float* __restrict__ ke)
{
    __shared__ float As[128 * KCP];
    __shared__ float Bs[TT * KCP];

    const int tid = threadIdx.x;
    const int wid = tid >> 5, lane = tid & 31;
    const int g = lane >> 2, t = lane & 3;
    const int warp_m = wid & 3;
    const int warp_n = wid >> 2;
    const int l0 = blockIdx.x * 128;
    const int bh = blockIdx.y;
    const int h  = bh % NH;

    float acc[2][6][4];
#pragma unroll
    for (int mf = 0; mf < 2; ++mf)
#pragma unroll
        for (int nf = 0; nf < 6; ++nf)
#pragma unroll
            for (int c = 0; c < 4; ++c) acc[mf][nf][c] = 0.f;

    const int mbase = warp_m * 32;
    const int nbase = warp_n * 48;

    for (int c = 0; c < 4; ++c) {
        const float* Asrc = (c < 2 ? g_Q : g_K) + ((size_t)bh * L + l0) * D + (c & 1) * 32;
        const float* E1 = (c < 2) ? qh : kh;
        const float* E2 = (c < 2) ? qe : ke;
        const int koff = h * D + (c & 1) * 32;

#pragma unroll
        for (int it = 0; it < 4; ++it) {
            int idx = tid + it * 256;
            int r = idx >> 3, v = (idx & 7) << 2;
            float4 a = *(const float4*)&Asrc[(size_t)r * D + v];
            float* da = &As[r * KCP + v];
            da[0] = f2tf32f(a.x); da[1] = f2tf32f(a.y);
            da[2] = f2tf32f(a.z); da[3] = f2tf32f(a.w);
        }
#pragma unroll
        for (int it = 0; it < 3; ++it) {
            int idx = tid + it * 256;
            int r = idx >> 3, v = (idx & 7) << 2;
            const float* src = (r < TH) ? &E1[(size_t)r * HID + koff + v]
                                        : &E2[(size_t)(r - TH) * HID + koff + v];
            float4 b = *(const float4*)src;
            float* db = &Bs[r * KCP + v];
            db[0] = f2tf32f(b.x); db[1] = f2tf32f(b.y);
            db[2] = f2tf32f(b.z); db[3] = f2tf32f(b.w);
        }
        __syncthreads();

#pragma unroll
        for (int kk = 0; kk < KC; kk += 8) {
            uint32_t bfr[6][2];
#pragma unroll
            for (int nf = 0; nf < 6; ++nf) {
                const float* bp = &Bs[(nbase + nf * 8 + g) * KCP + kk + t];
                bfr[nf][0] = __float_as_uint(bp[0]);
                bfr[nf][1] = __float_as_uint(bp[4]);
            }
            uint32_t afr[2][4];
#pragma unroll
            for (int mf = 0; mf < 2; ++mf) {
                const float* ap = &As[(mbase + mf * 16 + g) * KCP + kk + t];
                afr[mf][0] = __float_as_uint(ap[0]);
                afr[mf][1] = __float_as_uint(ap[8 * KCP]);
                afr[mf][2] = __float_as_uint(ap[4]);
                afr[mf][3] = __float_as_uint(ap[8 * KCP + 4]);
            }
#pragma unroll
            for (int mf = 0; mf < 2; ++mf)
#pragma unroll
                for (int nf = 0; nf < 6; ++nf)
                    mma_tf32(acc[mf][nf], afr[mf], bfr[nf]);
        }
        __syncthreads();
    }

    float* Pout = g_P + ((size_t)bh * L + l0) * TT;
#pragma unroll
    for (int mf = 0; mf < 2; ++mf) {
#pragma unroll
        for (int nf = 0; nf < 6; ++nf) {
            int row_a = mbase + mf * 16 + g;
            int col_a = nbase + nf * 8 + 2 * t;
#pragma unroll
            for (int half = 0; half < 2; ++half) {
                int row = row_a + half * 8;
                float2 v;
                v.x = acc[mf][nf][2 * half];
                v.y = acc[mf][nf][2 * half + 1];
                *(float2*)&Pout[(size_t)row * TT + col_a] = v;
            }
        }
    }
}

// ---------------- attention: mma phases, 512 threads, gather prefetch ------
#define AT_ROWS 32
#define QS_STR 68
#define KB_STR 68
#define VT_STR 132
#define ES_STR 132
#define BIN_STR 100
#define ATT_SMEM_FLOATS (AT_ROWS*QS_STR + AT_ROWS*TT + AT_ROWS*2*BIN_STR + AT_ROWS*ES_STR + 128*KB_STR + 32)

__global__ __launch_bounds__(512) void attn_kernel(
    const int* __restrict__ hop, const int* __restrict__ edge,
    const float* __restrict__ vh, const float* __restrict__ ve)
{
    extern __shared__ float sm[];
    float* qs   = sm;                            // [32][68] tf32 Q
    float* Ps   = qs + AT_ROWS * QS_STR;         // [32][96]
    float* bins = Ps + AT_ROWS * TT;             // [32][2][100]
    float* es   = bins + AT_ROWS * 2 * BIN_STR;  // [32][132] tf32 e
    float* buf  = es + AT_ROWS * ES_STR;         // K rows / V^T / VE / reduce
    float* rs   = buf + 128 * KB_STR;            // [32]
    float* binsC = es;                           // overlay after main loop

    const int bh = blockIdx.y;
    const int bb = bh / NH, h = bh % NH;
    const int i0 = blockIdx.x * AT_ROWS;
    const int tid = threadIdx.x;
    const int wid = tid >> 5, lane = tid & 31;
    const int g = lane >> 2, t = lane & 3;
    const float scale = 0.125f;

    {
        const float* Qp = g_Q + ((size_t)bh * L + i0) * D;
        for (int idx = tid; idx < AT_ROWS * D; idx += 512) {
            int row = idx >> 6, dd = idx & 63;
            qs[row * QS_STR + dd] = f2tf32f(Qp[idx]);
        }
        const float* Pp = g_P + ((size_t)bh * L + i0) * TT;
        for (int idx = tid; idx < AT_ROWS * TT; idx += 512) Ps[idx] = Pp[idx];
        for (int idx = tid; idx < AT_ROWS * 2 * BIN_STR; idx += 512) bins[idx] = 0.f;
        if (tid < 32) rs[tid] = 0.f;
    }
    __syncthreads();

    const size_t hopBase = ((size_t)bb * L + i0) * L;
    const int nsc = wid * 8;          // scores: 8 cols per warp (16 warps x 8 = 128)
    const int nav = (wid & 7) * 8;    // AV/VE: 8 d-cols, k split by jh
    const int jh  = wid >> 3;         // k-half selector
    const int rep = wid & 1;

    float oacc[2][4];
#pragma unroll
    for (int mf = 0; mf < 2; ++mf)
#pragma unroll
        for (int c = 0; c < 4; ++c) oacc[mf][c] = 0.f;
    float lsum[4] = {0.f, 0.f, 0.f, 0.f};

    for (int jc = 0; jc < L; jc += 128) {
        // ---- stage K chunk rows (tf32): buf[j][d], stride 68 ----
        {
            const float* Kp = g_K + ((size_t)bh * L + jc) * D;
            for (int idx4 = tid; idx4 < 2048; idx4 += 512) {
                int jj = idx4 >> 4, dd4 = (idx4 & 15) << 2;
                float4 kv = *(const float4*)&Kp[(size_t)jj * D + dd4];
                kv.x = f2tf32f(kv.x); kv.y = f2tf32f(kv.y);
                kv.z = f2tf32f(kv.z); kv.w = f2tf32f(kv.w);
                *(float4*)&buf[jj * KB_STR + dd4] = kv;
            }
        }
        __syncthreads();

        // ---- prefetch hop/edge gathers (overlap with scores mma) ----
        int2 hpre[2][2], epre[2][2];
        {
            int jl = nsc + 2 * t;
#pragma unroll
            for (int mf = 0; mf < 2; ++mf)
#pragma unroll
                for (int half = 0; half < 2; ++half) {
                    int i = mf * 16 + half * 8 + g;
                    size_t a = hopBase + (size_t)i * L + jc + jl;
                    hpre[mf][half] = *(const int2*)&hop [a];
                    epre[mf][half] = *(const int2*)&edge[a];
                }
        }

        // ---- scores mma: S[32][8 cols of this warp] ----
        float sacc[2][4];
#pragma unroll
        for (int mf = 0; mf < 2; ++mf)
#pragma unroll
            for (int c = 0; c < 4; ++c) sacc[mf][c] = 0.f;

#pragma unroll
        for (int ks = 0; ks < 8; ++ks) {
            int kk = ks * 8;
            uint32_t afr[2][4];
#pragma unroll
            for (int mf = 0; mf < 2; ++mf) {
                const float* ap = &qs[(mf * 16 + g) * QS_STR + kk + t];
                afr[mf][0] = __float_as_uint(ap[0]);
                afr[mf][1] = __float_as_uint(ap[8 * QS_STR]);
                afr[mf][2] = __float_as_uint(ap[4]);
                afr[mf][3] = __float_as_uint(ap[8 * QS_STR + 4]);
            }
            uint32_t bfr[2];
            {
                const float* bp = &buf[(nsc + g) * KB_STR + kk + t];
                bfr[0] = __float_as_uint(bp[0]);
                bfr[1] = __float_as_uint(bp[4]);
            }
#pragma unroll
            for (int mf = 0; mf < 2; ++mf)
                mma_tf32(sacc[mf], afr[mf], bfr);
        }

        // ---- bias add + exp + es store + bin scatter ----
        {
            int jl = nsc + 2 * t;
#pragma unroll
            for (int mf = 0; mf < 2; ++mf) {
#pragma unroll
                for (int half = 0; half < 2; ++half) {
                    int i = mf * 16 + half * 8 + g;
                    const int2 hp = hpre[mf][half];
                    const int2 ep = epre[mf][half];
                    const float* prow = Ps + i * TT;
                    float s0 = (sacc[mf][2*half]   + prow[hp.x] + prow[TH + ep.x]) * scale;
                    float s1 = (sacc[mf][2*half+1] + prow[hp.y] + prow[TH + ep.y]) * scale;
                    float e0 = __expf(fminf(fmaxf(s0, -70.f), 70.f));
                    float e1 = __expf(fminf(fmaxf(s1, -70.f), 70.f));
                    float2 ev = make_float2(f2tf32f(e0), f2tf32f(e1));
                    *(float2*)&es[i * ES_STR + jl] = ev;
                    lsum[mf * 2 + half] += e0 + e1;
                    float* brow = bins + (i * 2 + rep) * BIN_STR;
                    atomicAdd(&brow[hp.x], e0);  atomicAdd(&brow[TH + ep.x], e0);
                    atomicAdd(&brow[hp.y], e1);  atomicAdd(&brow[TH + ep.y], e1);
                }
            }
        }
        __syncthreads();   // es complete; buf (K) free

        // ---- stage V^T (tf32): buf[d][j], stride 132 ----
        {
            const float* Vp = g_V + ((size_t)bh * L + jc) * D;
            for (int idx4 = tid; idx4 < 2048; idx4 += 512) {
                int jj = idx4 >> 4, dd4 = (idx4 & 15) << 2;
                float4 vv = *(const float4*)&Vp[(size_t)jj * D + dd4];
                buf[(dd4 + 0) * VT_STR + jj] = f2tf32f(vv.x);
                buf[(dd4 + 1) * VT_STR + jj] = f2tf32f(vv.y);
                buf[(dd4 + 2) * VT_STR + jj] = f2tf32f(vv.z);
                buf[(dd4 + 3) * VT_STR + jj] = f2tf32f(vv.w);
            }
        }
        __syncthreads();

        // ---- AV mma: k-half jh covers j = jh*64..+64 ----
#pragma unroll
        for (int ks = 0; ks < 8; ++ks) {
            int kk = jh * 64 + ks * 8;
            uint32_t bfr[2];
            {
                const float* bp = &buf[(nav + g) * VT_STR + kk + t];
                bfr[0] = __float_as_uint(bp[0]);
                bfr[1] = __float_as_uint(bp[4]);
            }
#pragma unroll
            for (int mf = 0; mf < 2; ++mf) {
                uint32_t afr[4];
                const float* ap = &es[(mf * 16 + g) * ES_STR + kk + t];
                afr[0] = __float_as_uint(ap[0]);
                afr[1] = __float_as_uint(ap[8 * ES_STR]);
                afr[2] = __float_as_uint(ap[4]);
                afr[3] = __float_as_uint(ap[8 * ES_STR + 4]);
                mma_tf32(oacc[mf], afr, bfr);
            }
        }
        __syncthreads();   // es + buf free for next chunk
    }

    // ---- row sums ----
    atomicAdd(&rs[g],      lsum[0]);
    atomicAdd(&rs[g + 8],  lsum[1]);
    atomicAdd(&rs[16 + g], lsum[2]);
    atomicAdd(&rs[24 + g], lsum[3]);
    __syncthreads();

    // ---- combine + round bins -> binsC; stage VE ----
    for (int idx = tid; idx < AT_ROWS * TT; idx += 512) {
        int row = idx / TT, tt = idx % TT;
        binsC[row * BIN_STR + tt] =
            f2tf32f(bins[(row * 2) * BIN_STR + tt] + bins[(row * 2 + 1) * BIN_STR + tt]);
    }
    for (int idx = tid; idx < TT * D; idx += 512) {
        int tt = idx >> 6, d2 = idx & 63;
        float v = (tt < TH) ? vh[(size_t)tt * HID + h * D + d2]
                            : ve[(size_t)(tt - TH) * HID + h * D + d2];
        buf[d2 * BIN_STR + tt] = f2tf32f(v);
    }
    __syncthreads();

    // ---- bins x VE mma: k-half jh covers t = jh*48..+48 ----
#pragma unroll
    for (int ks = 0; ks < 6; ++ks) {
        int kk = jh * 48 + ks * 8;
        uint32_t bfr[2];
        {
            const float* bp = &buf[(nav + g) * BIN_STR + kk + t];
            bfr[0] = __float_as_uint(bp[0]);
            bfr[1] = __float_as_uint(bp[4]);
        }
#pragma unroll
        for (int mf = 0; mf < 2; ++mf) {
            uint32_t afr[4];
            const float* ap = &binsC[(mf * 16 + g) * BIN_STR + kk + t];
            afr[0] = __float_as_uint(ap[0]);
            afr[1] = __float_as_uint(ap[8 * BIN_STR]);
            afr[2] = __float_as_uint(ap[4]);
            afr[3] = __float_as_uint(ap[8 * BIN_STR + 4]);
            mma_tf32(oacc[mf], afr, bfr);
        }
    }
    __syncthreads();

    // ---- reduce the two k-half partials via smem (buf reused) ----
    if (jh == 1) {
#pragma unroll
        for (int mf = 0; mf < 2; ++mf)
#pragma unroll
            for (int half = 0; half < 2; ++half) {
                int i = mf * 16 + half * 8 + g;
                *(float2*)&buf[i * KB_STR + nav + 2 * t] =
                    make_float2(oacc[mf][2 * half], oacc[mf][2 * half + 1]);
            }
    }
    __syncthreads();
    if (jh == 0) {
#pragma unroll
        for (int mf = 0; mf < 2; ++mf)
#pragma unroll
            for (int half = 0; half < 2; ++half) {
                int i = mf * 16 + half * 8 + g;
                float rinv = 1.f / rs[i];
                float2 p = *(const float2*)&buf[i * KB_STR + nav + 2 * t];
                float2 v;
                v.x = f2tf32f((oacc[mf][2 * half]     + p.x) * rinv);
                v.y = f2tf32f((oacc[mf][2 * half + 1] + p.y) * rinv);
                *(float2*)&g_AO[((size_t)bb * L + i0 + i) * HID + h * D + nav + 2 * t] = v;
            }
    }
}

// --------------------------------------------------------------------------
extern "C" void kernel_launch(void* const* d_in, const int* in_sizes, int n_in,
                              void* d_out, int out_size)
{
    const float* x   = (const float*)d_in[0];
    const float* qh  = (const float*)d_in[1];
    const float* qe  = (const float*)d_in[2];
    const float* kh  = (const float*)d_in[3];
    const float* ke  = (const float*)d_in[4];
    const float* vh  = (const float*)d_in[5];
    const float* ve  = (const float*)d_in[6];
    const int*   hop = (const int*)d_in[7];
    const int*   edg = (const int*)d_in[8];
    const float* Wq = (const float*)d_in[9];   const float* bq = (const float*)d_in[10];
    const float* Wk = (const float*)d_in[11];  const float* bk = (const float*)d_in[12];
    const float* Wv = (const float*)d_in[13];  const float* bv = (const float*)d_in[14];
    const float* Wo = (const float*)d_in[15];  const float* bo = (const float*)d_in[16];
    float* out = (float*)d_out;

    float *Qp, *Kp, *Vp, *AOp, *WTp, *X32p;
    cudaGetSymbolAddress((void**)&Qp,  g_Q);
    cudaGetSymbolAddress((void**)&Kp,  g_K);
    cudaGetSymbolAddress((void**)&Vp,  g_V);
    cudaGetSymbolAddress((void**)&AOp, g_AO);
    cudaGetSymbolAddress((void**)&WTp, g_WT);
    cudaGetSymbolAddress((void**)&X32p, g_X32);

    const int attSmem  = ATT_SMEM_FLOATS * (int)sizeof(float);
    const int gemmSmem = 4 * SSZ * (int)sizeof(float);
    cudaFuncSetAttribute(attn_kernel, cudaFuncAttributeMaxDynamicSharedMemorySize, attSmem);
    cudaFuncSetAttribute(gemm_mma_kernel, cudaFuncAttributeMaxDynamicSharedMemorySize, gemmSmem);

    round_kernel<<<ROWS * HID / 1024, 256>>>(x, X32p);
    transpose4_kernel<<<dim3(HID / 32, HID / 32, 4), dim3(32, 8)>>>(Wq, Wk, Wv, Wo, WTp);

    gemm_mma_kernel<<<dim3(ROWS / 128, 18), 256, gemmSmem>>>(
        X32p, WTp, bq, bk, bv, Qp, Kp, Vp, 6, 1);

    proj_mma_kernel<<<dim3(L / 128, BH), 256>>>(qh, qe, kh, ke);
    attn_kernel<<<dim3(L / AT_ROWS, BH), 512, attSmem>>>(hop, edg, vh, ve);

    gemm_mma_kernel<<<dim3(ROWS / 128, 6), 256, gemmSmem>>>(
        AOp, WTp + 3 * (size_t)HID * HID, bo, bo, bo, out, out, out, 6, 0);
}